// round 1
// baseline (speedup 1.0000x reference)
#include <cuda_runtime.h>
#include <math.h>
#include <stdint.h>

// ---------------- model constants ----------------
#define BATCH 16
#define LSEQ  1000
#define DMODEL 512
#define NH    8
#define DHD   64
#define NPAD  1024
#define PADL  24
#define ML    256     // landmarks
#define LMR   4       // NPAD/ML
#define FFD   2048
#define DEPTH 6
#define KC    33
#define QSCALE 0.125f
#define BH (BATCH*NH)

// ---------------- scratch (device globals; no allocation) ----------------
__device__ float g_h   [BATCH*LSEQ*DMODEL];
__device__ float g_x   [BATCH*NPAD*DMODEL];
__device__ float g_qkv [BATCH*NPAD*3*DMODEL];
__device__ float g_q   [BH*NPAD*DHD];
__device__ float g_k   [BH*NPAD*DHD];
__device__ float g_v   [BH*NPAD*DHD];
__device__ float g_ql  [BH*ML*DHD];
__device__ float g_kl  [BH*ML*DHD];
__device__ float g_a1  [BH*NPAD*ML];
__device__ float g_a3  [BH*ML*NPAD];
__device__ float g_a2  [BH*ML*ML];
__device__ float g_zb  [BH*ML*ML];
__device__ float g_zb2 [BH*ML*ML];
__device__ float g_pb  [BH*ML*ML];
__device__ float g_tb  [BH*ML*ML];
__device__ float g_tb2 [BH*ML*ML];
__device__ float g_kvb [BH*ML*DHD];
__device__ float g_a1z [BH*NPAD*ML];
__device__ float g_ao  [BH*NPAD*DHD];
__device__ float g_y   [BATCH*NPAD*DMODEL];
__device__ float g_x2  [BATCH*LSEQ*DMODEL];
__device__ float g_ff  [BATCH*LSEQ*FFD];
__device__ int   g_red [2];

// ---------------- reductions ----------------
__device__ __forceinline__ float warpSum(float v){
    #pragma unroll
    for (int o=16;o;o>>=1) v += __shfl_xor_sync(0xffffffffu, v, o);
    return v;
}
__device__ __forceinline__ float warpMax(float v){
    #pragma unroll
    for (int o=16;o;o>>=1) v = fmaxf(v, __shfl_xor_sync(0xffffffffu, v, o));
    return v;
}
__device__ __forceinline__ float blockSumN(float v, float* sh, int nw){
    int w = threadIdx.x>>5, l = threadIdx.x&31;
    v = warpSum(v);
    if (l==0) sh[w] = v;
    __syncthreads();
    if (w==0){
        float x = (l < nw) ? sh[l] : 0.f;
        x = warpSum(x);
        if (l==0) sh[0] = x;
    }
    __syncthreads();
    float r = sh[0];
    __syncthreads();
    return r;
}
__device__ __forceinline__ float blockMaxN(float v, float* sh, int nw){
    int w = threadIdx.x>>5, l = threadIdx.x&31;
    v = warpMax(v);
    if (l==0) sh[w] = v;
    __syncthreads();
    if (w==0){
        float x = (l < nw) ? sh[l] : -3.4e38f;
        x = warpMax(x);
        if (l==0) sh[0] = x;
    }
    __syncthreads();
    float r = sh[0];
    __syncthreads();
    return r;
}

// ---------------- generic tiled GEMM ----------------
// C[bz] (M x N) = alpha * A[bz] (M x K, row-major) @ B[bz]
//   TB=0: B is K x N row-major.   TB=1: B is N x K row-major (C = A @ B^T)
// EPI 0: C = val
// EPI 2: C = gelu(val + bias[c])
// EPI 3: C[r*ldc+c] += val + bias[c]                      (FF2 residual)
// EPI 4: pad-sliced residual: b=r/NPAD, nl=r%NPAD; if nl>=PADL:
//        C[(b*LSEQ + nl-PADL)*ldc + c] += val + bias[c]   (attn out proj)
template<int TB, int EPI>
__global__ void __launch_bounds__(256) gemm_kernel(
    int Ki,
    const float* __restrict__ A, int lda, long long sA,
    const float* __restrict__ Bm, int ldb, long long sB,
    float* __restrict__ C, int ldc, long long sC,
    float alpha, const float* __restrict__ bias)
{
    const int bz = blockIdx.z;
    A  += (long long)bz * sA;
    Bm += (long long)bz * sB;
    C  += (long long)bz * sC;
    const int row0 = blockIdx.y * 64;
    const int col0 = blockIdx.x * 64;
    __shared__ float As[16][68];
    __shared__ float Bs[16][68];
    const int tid = threadIdx.x;
    const int ty = tid >> 4, tx = tid & 15;
    const int ar = tid >> 2, akq = (tid & 3) << 2;

    float acc[4][4];
    #pragma unroll
    for (int i=0;i<4;i++)
        #pragma unroll
        for (int j=0;j<4;j++) acc[i][j]=0.f;

    for (int k0 = 0; k0 < Ki; k0 += 16) {
        float4 av = *(const float4*)(A + (long long)(row0+ar)*lda + k0 + akq);
        As[akq+0][ar]=av.x; As[akq+1][ar]=av.y; As[akq+2][ar]=av.z; As[akq+3][ar]=av.w;
        if (TB==0) {
            int bkk = tid >> 4, bc = (tid & 15) << 2;
            float4 bv = *(const float4*)(Bm + (long long)(k0+bkk)*ldb + col0 + bc);
            Bs[bkk][bc+0]=bv.x; Bs[bkk][bc+1]=bv.y; Bs[bkk][bc+2]=bv.z; Bs[bkk][bc+3]=bv.w;
        } else {
            int bc = tid >> 2, bkq = (tid & 3) << 2;
            float4 bv = *(const float4*)(Bm + (long long)(col0+bc)*ldb + k0 + bkq);
            Bs[bkq+0][bc]=bv.x; Bs[bkq+1][bc]=bv.y; Bs[bkq+2][bc]=bv.z; Bs[bkq+3][bc]=bv.w;
        }
        __syncthreads();
        #pragma unroll
        for (int kk=0;kk<16;kk++){
            float a[4], b[4];
            #pragma unroll
            for (int i=0;i<4;i++) a[i]=As[kk][ty+16*i];
            #pragma unroll
            for (int j=0;j<4;j++) b[j]=Bs[kk][tx+16*j];
            #pragma unroll
            for (int i=0;i<4;i++)
                #pragma unroll
                for (int j=0;j<4;j++)
                    acc[i][j] = fmaf(a[i], b[j], acc[i][j]);
        }
        __syncthreads();
    }

    #pragma unroll
    for (int i=0;i<4;i++){
        int r = row0 + ty + 16*i;
        #pragma unroll
        for (int j=0;j<4;j++){
            int c = col0 + tx + 16*j;
            float val = alpha * acc[i][j];
            if (EPI==0) {
                C[(long long)r*ldc + c] = val;
            } else if (EPI==2) {
                float xg = val + bias[c];
                C[(long long)r*ldc + c] = 0.5f*xg*(1.f+erff(xg*0.70710678118654752f));
            } else if (EPI==3) {
                C[(long long)r*ldc + c] += val + bias[c];
            } else if (EPI==4) {
                int bb = r / NPAD, nl = r % NPAD;
                if (nl >= PADL)
                    C[((long long)bb*LSEQ + (nl-PADL))*ldc + c] += val + bias[c];
            }
        }
    }
}

// ---------------- elementwise / small kernels ----------------
__global__ void embed_kernel(const int* __restrict__ x,
                             const float* __restrict__ emb,
                             const float* __restrict__ pos){
    long long idx = (long long)blockIdx.x*blockDim.x + threadIdx.x;
    if (idx >= (long long)BATCH*LSEQ*DMODEL) return;
    int d = (int)(idx % DMODEL);
    long long bl = idx / DMODEL;
    int l = (int)(bl % LSEQ);
    int tok = x[bl];
    g_h[idx] = emb[(long long)tok*DMODEL + d] + pos[(long long)l*DMODEL + d];
}

__global__ void zero_pad_kernel(){
    int idx = blockIdx.x*blockDim.x + threadIdx.x;
    if (idx >= BATCH*PADL*DMODEL) return;
    int d  = idx % DMODEL;
    int bp = idx / DMODEL;
    int b  = bp / PADL, p = bp % PADL;
    g_x[((long long)b*NPAD + p)*DMODEL + d] = 0.f;
}

// one block (256 thr) per token row; D=512 (2 elems/thread)
__global__ void ln_kernel(const float* __restrict__ in, float* __restrict__ out,
                          const float* __restrict__ gm, const float* __restrict__ bt,
                          int padmode){
    __shared__ float sh[8];
    int r = blockIdx.x;            // 0 .. BATCH*LSEQ-1
    int t = threadIdx.x;           // 256
    const float* p = in + (long long)r*DMODEL;
    float a  = p[t];
    float b2 = p[t+256];
    float s  = blockSumN(a+b2, sh, 8);
    float mu = s * (1.f/512.f);
    float da = a - mu, db = b2 - mu;
    float v  = blockSumN(da*da + db*db, sh, 8) * (1.f/512.f);
    float rstd = rsqrtf(v + 1e-5f);
    long long orow = padmode ? ((long long)(r/LSEQ)*NPAD + PADL + (r%LSEQ)) : (long long)r;
    float* q = out + orow*DMODEL;
    q[t]     = da*rstd*gm[t]     + bt[t];
    q[t+256] = db*rstd*gm[t+256] + bt[t+256];
}

__global__ void qkv_split_kernel(){
    long long idx = (long long)blockIdx.x*blockDim.x + threadIdx.x;
    if (idx >= (long long)BH*NPAD*DHD) return;
    int d = (int)(idx & 63);
    long long r = idx >> 6;              // (b*NH+h)*NPAD + n
    int n  = (int)(r % NPAD);
    int bh = (int)(r / NPAD);
    int h  = bh % NH, b = bh / NH;
    long long base = ((long long)b*NPAD + n)*(3*DMODEL) + h*DHD + d;
    g_q[idx] = g_qkv[base] * QSCALE;
    g_k[idx] = g_qkv[base + DMODEL];
    g_v[idx] = g_qkv[base + 2*DMODEL];
}

__global__ void landmark_kernel(){
    long long idx = (long long)blockIdx.x*blockDim.x + threadIdx.x;
    if (idx >= (long long)BH*ML*DHD) return;
    int d = (int)(idx & 63);
    long long r = idx >> 6;
    int m  = (int)(r % ML);
    int bh = (int)(r / ML);
    long long base = ((long long)bh*NPAD + (long long)m*LMR)*DHD + d;
    float sq = 0.f, sk = 0.f;
    #pragma unroll
    for (int j=0;j<LMR;j++){ sq += g_q[base + (long long)j*DHD]; sk += g_k[base + (long long)j*DHD]; }
    g_ql[idx] = sq * 0.25f;
    g_kl[idx] = sk * 0.25f;
}

// one block (128 thr) per row, cols in {256,1024}
__global__ void softmax_kernel(float* __restrict__ X, int cols){
    __shared__ float sh[4];
    long long row = blockIdx.x;
    float* p = X + row*(long long)cols;
    int t = threadIdx.x;
    int cnt = cols >> 7;
    float v[8];
    float mx = -3.4e38f;
    #pragma unroll
    for (int i=0;i<8;i++) if (i<cnt){ v[i]=p[t + (i<<7)]; mx = fmaxf(mx, v[i]); }
    mx = blockMaxN(mx, sh, 4);
    float s = 0.f;
    #pragma unroll
    for (int i=0;i<8;i++) if (i<cnt){ v[i]=expf(v[i]-mx); s += v[i]; }
    s = blockSumN(s, sh, 4);
    float inv = 1.f/s;
    #pragma unroll
    for (int i=0;i<8;i++) if (i<cnt) p[t + (i<<7)] = v[i]*inv;
}

__global__ void red_init_kernel(){ g_red[0]=0; g_red[1]=0; }

__global__ void colsum_kernel(){
    int idx = blockIdx.x*blockDim.x + threadIdx.x;   // BH*ML
    if (idx >= BH*ML) return;
    int c  = idx % ML;
    int bz = idx / ML;
    const float* p = g_a2 + (long long)bz*ML*ML + c;
    float s = 0.f;
    for (int r2=0;r2<ML;r2++) s += fabsf(p[(long long)r2*ML]);
    atomicMax(&g_red[0], __float_as_int(s));
}
__global__ void rowsum_kernel(){
    int idx = blockIdx.x*blockDim.x + threadIdx.x;   // BH*ML
    if (idx >= BH*ML) return;
    int r2 = idx % ML;
    int bz = idx / ML;
    const float* p = g_a2 + (long long)bz*ML*ML + (long long)r2*ML;
    float s = 0.f;
    for (int c=0;c<ML;c++) s += fabsf(p[c]);
    atomicMax(&g_red[1], __float_as_int(s));
}
__global__ void zinit_kernel(){
    long long idx = (long long)blockIdx.x*blockDim.x + threadIdx.x;
    if (idx >= (long long)BH*ML*ML) return;
    int j = (int)(idx % ML);
    long long r = idx / ML;
    int i  = (int)(r % ML);
    int bz = (int)(r / ML);
    float c = __int_as_float(g_red[0]) * __int_as_float(g_red[1]);
    g_zb[idx] = g_a2[((long long)bz*ML + j)*ML + i] / c;
}

// T = a*I - P
__global__ void aimx_kernel(float a, const float* __restrict__ P, float* __restrict__ T){
    long long idx = (long long)blockIdx.x*blockDim.x + threadIdx.x;
    if (idx >= (long long)BH*ML*ML) return;
    int j = (int)(idx % ML);
    int i = (int)((idx / ML) % ML);
    T[idx] = (i==j ? a : 0.f) - P[idx];
}

// y[b,n,h*64+d] = ao[b,h,n,d] + depthwise_conv(v)[b,h,n,d]
__global__ void combine_kernel(const float* __restrict__ cw){
    long long idx = (long long)blockIdx.x*blockDim.x + threadIdx.x;
    if (idx >= (long long)BH*NPAD*DHD) return;
    int d = (int)(idx & 63);
    long long r = idx >> 6;
    int n  = (int)(r % NPAD);
    int bh = (int)(r / NPAD);
    int h  = bh % NH, b = bh / NH;
    float s = g_ao[idx];
    const float* w  = cw + h*KC;
    const float* vp = g_v + ((long long)bh*NPAD)*DHD + d;
    int k0 = (16-n > 0) ? (16-n) : 0;
    int k1 = (NPAD+16-n < KC) ? (NPAD+16-n) : KC;
    for (int kk=k0; kk<k1; kk++)
        s = fmaf(vp[(long long)(n+kk-16)*DHD], w[kk], s);
    g_y[((long long)b*NPAD + n)*DMODEL + h*DHD + d] = s;
}

__global__ void final_kernel(const float* __restrict__ fw,
                             const float* __restrict__ fb,
                             float* __restrict__ out){
    __shared__ float sh[8];
    int b = blockIdx.x;
    int t = threadIdx.x;  // 256
    const float* hp = g_h + (long long)b*LSEQ*DMODEL;
    float s = 0.f;
    for (long long i=t; i<(long long)LSEQ*DMODEL; i+=256)
        s = fmaf(hp[i], fw[i], s);
    s = blockSumN(s, sh, 8);
    if (t==0) out[b] = s + fb[0];
}

// ---------------- host-side GEMM dispatch ----------------
static void run_gemm(int tb, int epi, int Mi, int Ni, int Ki,
                     const float* A, int lda, long long sA,
                     const float* Bm, int ldb, long long sB,
                     float* C, int ldc, long long sC,
                     int batch, float alpha, const float* bias)
{
    dim3 g(Ni/64, Mi/64, batch), t(256);
    if (tb==0){
        if      (epi==0) gemm_kernel<0,0><<<g,t>>>(Ki,A,lda,sA,Bm,ldb,sB,C,ldc,sC,alpha,bias);
        else if (epi==2) gemm_kernel<0,2><<<g,t>>>(Ki,A,lda,sA,Bm,ldb,sB,C,ldc,sC,alpha,bias);
        else if (epi==3) gemm_kernel<0,3><<<g,t>>>(Ki,A,lda,sA,Bm,ldb,sB,C,ldc,sC,alpha,bias);
        else             gemm_kernel<0,4><<<g,t>>>(Ki,A,lda,sA,Bm,ldb,sB,C,ldc,sC,alpha,bias);
    } else {
        gemm_kernel<1,0><<<g,t>>>(Ki,A,lda,sA,Bm,ldb,sB,C,ldc,sC,alpha,bias);
    }
}

extern "C" void kernel_launch(void* const* d_in, const int* in_sizes, int n_in,
                              void* d_out, int out_size)
{
    (void)in_sizes; (void)n_in; (void)out_size;
    const int*   x       = (const int*)  d_in[0];
    const float* enc_emb = (const float*)d_in[1];
    const float* pos_emb = (const float*)d_in[2];
    const float* ln1_s   = (const float*)d_in[3];
    const float* ln1_b   = (const float*)d_in[4];
    const float* qkv_w   = (const float*)d_in[5];
    const float* aout_w  = (const float*)d_in[6];
    const float* aout_b  = (const float*)d_in[7];
    const float* conv_k  = (const float*)d_in[8];
    const float* ln2_s   = (const float*)d_in[9];
    const float* ln2_b   = (const float*)d_in[10];
    const float* ff_w1   = (const float*)d_in[11];
    const float* ff_b1   = (const float*)d_in[12];
    const float* ff_w2   = (const float*)d_in[13];
    const float* ff_b2   = (const float*)d_in[14];
    const float* fin_w   = (const float*)d_in[15];
    const float* fin_b   = (const float*)d_in[16];
    float* out = (float*)d_out;

    float *p_h,*p_x,*p_qkv,*p_q,*p_k,*p_v,*p_ql,*p_kl,*p_a1,*p_a3,*p_a2;
    float *p_z,*p_z2,*p_p,*p_t,*p_t2,*p_kv,*p_a1z,*p_ao,*p_y,*p_x2,*p_ff;
    cudaGetSymbolAddress((void**)&p_h,  g_h);
    cudaGetSymbolAddress((void**)&p_x,  g_x);
    cudaGetSymbolAddress((void**)&p_qkv,g_qkv);
    cudaGetSymbolAddress((void**)&p_q,  g_q);
    cudaGetSymbolAddress((void**)&p_k,  g_k);
    cudaGetSymbolAddress((void**)&p_v,  g_v);
    cudaGetSymbolAddress((void**)&p_ql, g_ql);
    cudaGetSymbolAddress((void**)&p_kl, g_kl);
    cudaGetSymbolAddress((void**)&p_a1, g_a1);
    cudaGetSymbolAddress((void**)&p_a3, g_a3);
    cudaGetSymbolAddress((void**)&p_a2, g_a2);
    cudaGetSymbolAddress((void**)&p_z,  g_zb);
    cudaGetSymbolAddress((void**)&p_z2, g_zb2);
    cudaGetSymbolAddress((void**)&p_p,  g_pb);
    cudaGetSymbolAddress((void**)&p_t,  g_tb);
    cudaGetSymbolAddress((void**)&p_t2, g_tb2);
    cudaGetSymbolAddress((void**)&p_kv, g_kvb);
    cudaGetSymbolAddress((void**)&p_a1z,g_a1z);
    cudaGetSymbolAddress((void**)&p_ao, g_ao);
    cudaGetSymbolAddress((void**)&p_y,  g_y);
    cudaGetSymbolAddress((void**)&p_x2, g_x2);
    cudaGetSymbolAddress((void**)&p_ff, g_ff);

    const long long MM  = (long long)ML*ML;
    const long long NM  = (long long)NPAD*ML;
    const long long ND  = (long long)NPAD*DHD;
    const long long MD  = (long long)ML*DHD;

    {
        long long tot = (long long)BATCH*LSEQ*DMODEL;
        embed_kernel<<<(unsigned)((tot+255)/256),256>>>(x, enc_emb, pos_emb);
        int tot2 = BATCH*PADL*DMODEL;
        zero_pad_kernel<<<(tot2+255)/256,256>>>();
    }

    for (int lay=0; lay<DEPTH; lay++){
        // LN1 -> padded g_x
        ln_kernel<<<BATCH*LSEQ,256>>>(p_h, p_x, ln1_s+(long long)lay*DMODEL, ln1_b+(long long)lay*DMODEL, 1);
        // QKV gemm: (B*N,512) @ (512,1536)
        run_gemm(0,0, BATCH*NPAD, 3*DMODEL, DMODEL,
                 p_x, DMODEL, 0,
                 qkv_w + (long long)lay*DMODEL*3*DMODEL, 3*DMODEL, 0,
                 p_qkv, 3*DMODEL, 0, 1, 1.f, nullptr);
        {
            long long tot = (long long)BH*NPAD*DHD;
            qkv_split_kernel<<<(unsigned)((tot+255)/256),256>>>();
            long long tot2 = (long long)BH*ML*DHD;
            landmark_kernel<<<(unsigned)((tot2+255)/256),256>>>();
        }
        // attn1 = softmax(q @ kl^T): 1024x256, K=64, batched 128
        run_gemm(1,0, NPAD, ML, DHD, p_q, DHD, ND, p_kl, DHD, MD, p_a1, ML, NM, BH, 1.f, nullptr);
        softmax_kernel<<<BH*NPAD,128>>>(p_a1, ML);
        // attn2 = softmax(ql @ kl^T): 256x256
        run_gemm(1,0, ML, ML, DHD, p_ql, DHD, MD, p_kl, DHD, MD, p_a2, ML, MM, BH, 1.f, nullptr);
        softmax_kernel<<<BH*ML,128>>>(p_a2, ML);
        // attn3 = softmax(ql @ k^T): 256x1024
        run_gemm(1,0, ML, NPAD, DHD, p_ql, DHD, MD, p_k, DHD, ND, p_a3, NPAD, MM*0 + (long long)ML*NPAD, BH, 1.f, nullptr);
        softmax_kernel<<<BH*ML,128>>>(p_a3, NPAD);

        // ---- Moore-Penrose pinv of attn2 ----
        red_init_kernel<<<1,1>>>();
        colsum_kernel<<<(BH*ML+255)/256,256>>>();
        rowsum_kernel<<<(BH*ML+255)/256,256>>>();
        {
            long long tot = (long long)BH*ML*ML;
            unsigned g = (unsigned)((tot+255)/256);
            zinit_kernel<<<g,256>>>();
        }
        float* zc = p_z; float* zn = p_z2;
        long long totMM = (long long)BH*ML*ML;
        unsigned gMM = (unsigned)((totMM+255)/256);
        for (int it=0; it<6; it++){
            run_gemm(0,0, ML, ML, ML, p_a2, ML, MM, zc, ML, MM, p_p, ML, MM, BH, 1.f, nullptr);
            aimx_kernel<<<gMM,256>>>(7.f, p_p, p_t);
            run_gemm(0,0, ML, ML, ML, p_p, ML, MM, p_t, ML, MM, p_t2, ML, MM, BH, 1.f, nullptr);
            aimx_kernel<<<gMM,256>>>(15.f, p_t2, p_t);
            run_gemm(0,0, ML, ML, ML, p_p, ML, MM, p_t, ML, MM, p_t2, ML, MM, BH, 1.f, nullptr);
            aimx_kernel<<<gMM,256>>>(13.f, p_t2, p_t);
            run_gemm(0,0, ML, ML, ML, zc, ML, MM, p_t, ML, MM, zn, ML, MM, BH, 0.25f, nullptr);
            float* tmp = zc; zc = zn; zn = tmp;
        }

        // kv = attn3 @ v : 256x64, K=1024
        run_gemm(0,0, ML, DHD, NPAD, p_a3, NPAD, (long long)ML*NPAD, p_v, DHD, ND, p_kv, DHD, MD, BH, 1.f, nullptr);
        // a1z = attn1 @ Z : 1024x256, K=256
        run_gemm(0,0, NPAD, ML, ML, p_a1, ML, NM, zc, ML, MM, p_a1z, ML, NM, BH, 1.f, nullptr);
        // ao = a1z @ kv : 1024x64, K=256
        run_gemm(0,0, NPAD, DHD, ML, p_a1z, ML, NM, p_kv, DHD, MD, p_ao, DHD, ND, BH, 1.f, nullptr);
        // combine attn out + depthwise conv(v), transpose to (B,N,D)
        {
            long long tot = (long long)BH*NPAD*DHD;
            combine_kernel<<<(unsigned)((tot+255)/256),256>>>(conv_k + (long long)lay*NH*KC);
        }
        // out projection + residual into h (pad-sliced)
        run_gemm(0,4, BATCH*NPAD, DMODEL, DMODEL,
                 p_y, DMODEL, 0,
                 aout_w + (long long)lay*DMODEL*DMODEL, DMODEL, 0,
                 p_h, DMODEL, 0, 1, 1.f, aout_b + (long long)lay*DMODEL);

        // ---- FFN ----
        ln_kernel<<<BATCH*LSEQ,256>>>(p_h, p_x2, ln2_s+(long long)lay*DMODEL, ln2_b+(long long)lay*DMODEL, 0);
        run_gemm(0,2, BATCH*LSEQ, FFD, DMODEL,
                 p_x2, DMODEL, 0,
                 ff_w1 + (long long)lay*DMODEL*FFD, FFD, 0,
                 p_ff, FFD, 0, 1, 1.f, ff_b1 + (long long)lay*FFD);
        run_gemm(0,3, BATCH*LSEQ, DMODEL, FFD,
                 p_ff, FFD, 0,
                 ff_w2 + (long long)lay*FFD*DMODEL, DMODEL, 0,
                 p_h, DMODEL, 0, 1, 1.f, ff_b2 + (long long)lay*DMODEL);
    }

    final_kernel<<<BATCH,256>>>(fin_w, fin_b, out);
}

// round 2
// speedup vs baseline: 1.4162x; 1.4162x over previous
#include <cuda_runtime.h>
#include <math.h>
#include <stdint.h>

// ---------------- model constants ----------------
#define BATCH 16
#define LSEQ  1000
#define DMODEL 512
#define NH    8
#define DHD   64
#define NPAD  1024
#define PADL  24
#define ML    256     // landmarks
#define LMR   4       // NPAD/ML
#define FFD   2048
#define DEPTH 6
#define KC    33
#define QSCALE 0.125f
#define BH (BATCH*NH)

// ---------------- scratch (device globals; no allocation) ----------------
__device__ float g_h   [BATCH*LSEQ*DMODEL];
__device__ float g_x   [BATCH*NPAD*DMODEL];
__device__ float g_qkv [BATCH*NPAD*3*DMODEL];
__device__ float g_q   [BH*NPAD*DHD];
__device__ float g_k   [BH*NPAD*DHD];
__device__ float g_v   [BH*NPAD*DHD];
__device__ float g_ql  [BH*ML*DHD];
__device__ float g_kl  [BH*ML*DHD];
__device__ float g_a1  [BH*NPAD*ML];
__device__ float g_a3  [BH*ML*NPAD];
__device__ float g_a2  [BH*ML*ML];
__device__ float g_zb  [BH*ML*ML];
__device__ float g_zb2 [BH*ML*ML];
__device__ float g_pb  [BH*ML*ML];
__device__ float g_tb  [BH*ML*ML];
__device__ float g_tb2 [BH*ML*ML];
__device__ float g_kvb [BH*ML*DHD];
__device__ float g_a1z [BH*NPAD*ML];
__device__ float g_ao  [BH*NPAD*DHD];
__device__ float g_y   [BATCH*NPAD*DMODEL];
__device__ float g_x2  [BATCH*LSEQ*DMODEL];
__device__ float g_ff  [BATCH*LSEQ*FFD];
__device__ int   g_red [2];

// ---------------- reductions ----------------
__device__ __forceinline__ float warpSum(float v){
    #pragma unroll
    for (int o=16;o;o>>=1) v += __shfl_xor_sync(0xffffffffu, v, o);
    return v;
}
__device__ __forceinline__ float warpMax(float v){
    #pragma unroll
    for (int o=16;o;o>>=1) v = fmaxf(v, __shfl_xor_sync(0xffffffffu, v, o));
    return v;
}
__device__ __forceinline__ float blockSumN(float v, float* sh, int nw){
    int w = threadIdx.x>>5, l = threadIdx.x&31;
    v = warpSum(v);
    if (l==0) sh[w] = v;
    __syncthreads();
    if (w==0){
        float x = (l < nw) ? sh[l] : 0.f;
        x = warpSum(x);
        if (l==0) sh[0] = x;
    }
    __syncthreads();
    float r = sh[0];
    __syncthreads();
    return r;
}
__device__ __forceinline__ float blockMaxN(float v, float* sh, int nw){
    int w = threadIdx.x>>5, l = threadIdx.x&31;
    v = warpMax(v);
    if (l==0) sh[w] = v;
    __syncthreads();
    if (w==0){
        float x = (l < nw) ? sh[l] : -3.4e38f;
        x = warpMax(x);
        if (l==0) sh[0] = x;
    }
    __syncthreads();
    float r = sh[0];
    __syncthreads();
    return r;
}

// ================= 128x128x8 double-buffered SGEMM (8x8 per thread) ========
// C[bz] (M x N) = alpha * A[bz] (MxK rm) @ B[bz] (KxN rm)   [+ epilogue]
// Requires M%128==0, N%128==0, K%8==0.
// EPI 0: C = val
// EPI 2: C = gelu(val + bias[c])
// EPI 3: C += val + bias[c]
// EPI 4: pad-sliced residual add into h
template<int EPI>
__global__ void __launch_bounds__(256) gemm128_kernel(
    int Ki,
    const float* __restrict__ A, int lda, long long sA,
    const float* __restrict__ Bm, int ldb, long long sB,
    float* __restrict__ C, int ldc, long long sC,
    float alpha, const float* __restrict__ bias)
{
    __shared__ float As[2][8][132];
    __shared__ float Bs[2][8][128];

    const int bz = blockIdx.z;
    A  += (long long)bz * sA;
    Bm += (long long)bz * sB;
    C  += (long long)bz * sC;
    const int row0 = blockIdx.y * 128;
    const int col0 = blockIdx.x * 128;
    const int tid = threadIdx.x;

    const int arow = tid >> 1, acol = (tid & 1) << 2;
    const int brow = tid >> 5, bcol = (tid & 31) << 2;
    const float* Aptr = A  + (long long)(row0 + arow) * lda + acol;
    const float* Bptr = Bm + (long long)brow * ldb + col0 + bcol;

    float4 av = *(const float4*)Aptr;
    float4 bv = *(const float4*)Bptr;
    As[0][acol+0][arow] = av.x;
    As[0][acol+1][arow] = av.y;
    As[0][acol+2][arow] = av.z;
    As[0][acol+3][arow] = av.w;
    *(float4*)&Bs[0][brow][bcol] = bv;
    __syncthreads();

    float acc[8][8];
    #pragma unroll
    for (int i=0;i<8;i++)
        #pragma unroll
        for (int j=0;j<8;j++) acc[i][j]=0.f;

    const int ty = tid >> 4, tx = tid & 15;
    const int nk = Ki >> 3;
    int buf = 0;

    for (int t = 0; t < nk; ++t) {
        if (t + 1 < nk) {
            av = *(const float4*)(Aptr + (t+1)*8);
            bv = *(const float4*)(Bptr + (long long)(t+1)*8*ldb);
        }
        #pragma unroll
        for (int kk=0; kk<8; kk++){
            float4 a0 = *(const float4*)&As[buf][kk][ty*4];
            float4 a1 = *(const float4*)&As[buf][kk][64 + ty*4];
            float4 b0 = *(const float4*)&Bs[buf][kk][tx*4];
            float4 b1 = *(const float4*)&Bs[buf][kk][64 + tx*4];
            float a[8] = {a0.x,a0.y,a0.z,a0.w,a1.x,a1.y,a1.z,a1.w};
            float b[8] = {b0.x,b0.y,b0.z,b0.w,b1.x,b1.y,b1.z,b1.w};
            #pragma unroll
            for (int i=0;i<8;i++)
                #pragma unroll
                for (int j=0;j<8;j++)
                    acc[i][j] = fmaf(a[i], b[j], acc[i][j]);
        }
        if (t + 1 < nk) {
            As[buf^1][acol+0][arow] = av.x;
            As[buf^1][acol+1][arow] = av.y;
            As[buf^1][acol+2][arow] = av.z;
            As[buf^1][acol+3][arow] = av.w;
            *(float4*)&Bs[buf^1][brow][bcol] = bv;
        }
        __syncthreads();
        buf ^= 1;
    }

    #pragma unroll
    for (int i=0;i<8;i++){
        int r = row0 + ((i<4) ? (ty*4 + i) : (64 + ty*4 + i - 4));
        #pragma unroll
        for (int g=0; g<2; g++){
            int c = col0 + g*64 + tx*4;
            float4 v;
            v.x = alpha*acc[i][g*4+0];
            v.y = alpha*acc[i][g*4+1];
            v.z = alpha*acc[i][g*4+2];
            v.w = alpha*acc[i][g*4+3];
            if (EPI==0) {
                *(float4*)&C[(long long)r*ldc + c] = v;
            } else if (EPI==2) {
                float4 bb4 = *(const float4*)&bias[c];
                float4 o;
                float x0=v.x+bb4.x, x1=v.y+bb4.y, x2=v.z+bb4.z, x3=v.w+bb4.w;
                o.x = 0.5f*x0*(1.f+erff(x0*0.70710678118654752f));
                o.y = 0.5f*x1*(1.f+erff(x1*0.70710678118654752f));
                o.z = 0.5f*x2*(1.f+erff(x2*0.70710678118654752f));
                o.w = 0.5f*x3*(1.f+erff(x3*0.70710678118654752f));
                *(float4*)&C[(long long)r*ldc + c] = o;
            } else if (EPI==3) {
                float4 bb4 = *(const float4*)&bias[c];
                float4 o = *(float4*)&C[(long long)r*ldc + c];
                o.x += v.x + bb4.x; o.y += v.y + bb4.y;
                o.z += v.z + bb4.z; o.w += v.w + bb4.w;
                *(float4*)&C[(long long)r*ldc + c] = o;
            } else if (EPI==4) {
                int bb = r / NPAD, nl = r % NPAD;
                if (nl >= PADL) {
                    float4 bb4 = *(const float4*)&bias[c];
                    long long orow = (long long)bb*LSEQ + (nl - PADL);
                    float4 o = *(float4*)&C[orow*ldc + c];
                    o.x += v.x + bb4.x; o.y += v.y + bb4.y;
                    o.z += v.z + bb4.z; o.w += v.w + bb4.w;
                    *(float4*)&C[orow*ldc + c] = o;
                }
            }
        }
    }
}

// ---------------- generic 64x64 tiled GEMM (for small-N / transposed-B) ----
template<int TB, int EPI>
__global__ void __launch_bounds__(256) gemm_kernel(
    int Ki,
    const float* __restrict__ A, int lda, long long sA,
    const float* __restrict__ Bm, int ldb, long long sB,
    float* __restrict__ C, int ldc, long long sC,
    float alpha, const float* __restrict__ bias)
{
    const int bz = blockIdx.z;
    A  += (long long)bz * sA;
    Bm += (long long)bz * sB;
    C  += (long long)bz * sC;
    const int row0 = blockIdx.y * 64;
    const int col0 = blockIdx.x * 64;
    __shared__ float As[16][68];
    __shared__ float Bs[16][68];
    const int tid = threadIdx.x;
    const int ty = tid >> 4, tx = tid & 15;
    const int ar = tid >> 2, akq = (tid & 3) << 2;

    float acc[4][4];
    #pragma unroll
    for (int i=0;i<4;i++)
        #pragma unroll
        for (int j=0;j<4;j++) acc[i][j]=0.f;

    for (int k0 = 0; k0 < Ki; k0 += 16) {
        float4 av = *(const float4*)(A + (long long)(row0+ar)*lda + k0 + akq);
        As[akq+0][ar]=av.x; As[akq+1][ar]=av.y; As[akq+2][ar]=av.z; As[akq+3][ar]=av.w;
        if (TB==0) {
            int bkk = tid >> 4, bc = (tid & 15) << 2;
            float4 bv = *(const float4*)(Bm + (long long)(k0+bkk)*ldb + col0 + bc);
            Bs[bkk][bc+0]=bv.x; Bs[bkk][bc+1]=bv.y; Bs[bkk][bc+2]=bv.z; Bs[bkk][bc+3]=bv.w;
        } else {
            int bc = tid >> 2, bkq = (tid & 3) << 2;
            float4 bv = *(const float4*)(Bm + (long long)(col0+bc)*ldb + k0 + bkq);
            Bs[bkq+0][bc]=bv.x; Bs[bkq+1][bc]=bv.y; Bs[bkq+2][bc]=bv.z; Bs[bkq+3][bc]=bv.w;
        }
        __syncthreads();
        #pragma unroll
        for (int kk=0;kk<16;kk++){
            float a[4], b[4];
            #pragma unroll
            for (int i=0;i<4;i++) a[i]=As[kk][ty+16*i];
            #pragma unroll
            for (int j=0;j<4;j++) b[j]=Bs[kk][tx+16*j];
            #pragma unroll
            for (int i=0;i<4;i++)
                #pragma unroll
                for (int j=0;j<4;j++)
                    acc[i][j] = fmaf(a[i], b[j], acc[i][j]);
        }
        __syncthreads();
    }

    #pragma unroll
    for (int i=0;i<4;i++){
        int r = row0 + ty + 16*i;
        #pragma unroll
        for (int j=0;j<4;j++){
            int c = col0 + tx + 16*j;
            float val = alpha * acc[i][j];
            if (EPI==0) {
                C[(long long)r*ldc + c] = val;
            } else if (EPI==2) {
                float xg = val + bias[c];
                C[(long long)r*ldc + c] = 0.5f*xg*(1.f+erff(xg*0.70710678118654752f));
            } else if (EPI==3) {
                C[(long long)r*ldc + c] += val + bias[c];
            } else if (EPI==4) {
                int bb = r / NPAD, nl = r % NPAD;
                if (nl >= PADL)
                    C[((long long)bb*LSEQ + (nl-PADL))*ldc + c] += val + bias[c];
            }
        }
    }
}

// ---------------- elementwise / small kernels ----------------
__global__ void embed_kernel(const int* __restrict__ x,
                             const float* __restrict__ emb,
                             const float* __restrict__ pos){
    long long idx = (long long)blockIdx.x*blockDim.x + threadIdx.x;
    if (idx >= (long long)BATCH*LSEQ*DMODEL) return;
    int d = (int)(idx % DMODEL);
    long long bl = idx / DMODEL;
    int l = (int)(bl % LSEQ);
    int tok = x[bl];
    g_h[idx] = emb[(long long)tok*DMODEL + d] + pos[(long long)l*DMODEL + d];
}

__global__ void zero_pad_kernel(){
    int idx = blockIdx.x*blockDim.x + threadIdx.x;
    if (idx >= BATCH*PADL*DMODEL) return;
    int d  = idx % DMODEL;
    int bp = idx / DMODEL;
    int b  = bp / PADL, p = bp % PADL;
    g_x[((long long)b*NPAD + p)*DMODEL + d] = 0.f;
}

// one block (256 thr) per token row; D=512 (2 elems/thread)
__global__ void ln_kernel(const float* __restrict__ in, float* __restrict__ out,
                          const float* __restrict__ gm, const float* __restrict__ bt,
                          int padmode){
    __shared__ float sh[8];
    int r = blockIdx.x;            // 0 .. BATCH*LSEQ-1
    int t = threadIdx.x;           // 256
    const float* p = in + (long long)r*DMODEL;
    float a  = p[t];
    float b2 = p[t+256];
    float s  = blockSumN(a+b2, sh, 8);
    float mu = s * (1.f/512.f);
    float da = a - mu, db = b2 - mu;
    float v  = blockSumN(da*da + db*db, sh, 8) * (1.f/512.f);
    float rstd = rsqrtf(v + 1e-5f);
    long long orow = padmode ? ((long long)(r/LSEQ)*NPAD + PADL + (r%LSEQ)) : (long long)r;
    float* q = out + orow*DMODEL;
    q[t]     = da*rstd*gm[t]     + bt[t];
    q[t+256] = db*rstd*gm[t+256] + bt[t+256];
}

__global__ void qkv_split_kernel(){
    long long idx = (long long)blockIdx.x*blockDim.x + threadIdx.x;
    if (idx >= (long long)BH*NPAD*DHD) return;
    int d = (int)(idx & 63);
    long long r = idx >> 6;              // (b*NH+h)*NPAD + n
    int n  = (int)(r % NPAD);
    int bh = (int)(r / NPAD);
    int h  = bh % NH, b = bh / NH;
    long long base = ((long long)b*NPAD + n)*(3*DMODEL) + h*DHD + d;
    g_q[idx] = g_qkv[base] * QSCALE;
    g_k[idx] = g_qkv[base + DMODEL];
    g_v[idx] = g_qkv[base + 2*DMODEL];
}

__global__ void landmark_kernel(){
    long long idx = (long long)blockIdx.x*blockDim.x + threadIdx.x;
    if (idx >= (long long)BH*ML*DHD) return;
    int d = (int)(idx & 63);
    long long r = idx >> 6;
    int m  = (int)(r % ML);
    int bh = (int)(r / ML);
    long long base = ((long long)bh*NPAD + (long long)m*LMR)*DHD + d;
    float sq = 0.f, sk = 0.f;
    #pragma unroll
    for (int j=0;j<LMR;j++){ sq += g_q[base + (long long)j*DHD]; sk += g_k[base + (long long)j*DHD]; }
    g_ql[idx] = sq * 0.25f;
    g_kl[idx] = sk * 0.25f;
}

// one block (128 thr) per row, cols in {256,1024}
__global__ void softmax_kernel(float* __restrict__ X, int cols){
    __shared__ float sh[4];
    long long row = blockIdx.x;
    float* p = X + row*(long long)cols;
    int t = threadIdx.x;
    int cnt = cols >> 7;
    float v[8];
    float mx = -3.4e38f;
    #pragma unroll
    for (int i=0;i<8;i++) if (i<cnt){ v[i]=p[t + (i<<7)]; mx = fmaxf(mx, v[i]); }
    mx = blockMaxN(mx, sh, 4);
    float s = 0.f;
    #pragma unroll
    for (int i=0;i<8;i++) if (i<cnt){ v[i]=expf(v[i]-mx); s += v[i]; }
    s = blockSumN(s, sh, 4);
    float inv = 1.f/s;
    #pragma unroll
    for (int i=0;i<8;i++) if (i<cnt) p[t + (i<<7)] = v[i]*inv;
}

__global__ void red_init_kernel(){ g_red[0]=0; g_red[1]=0; }

__global__ void colsum_kernel(){
    int idx = blockIdx.x*blockDim.x + threadIdx.x;   // BH*ML
    if (idx >= BH*ML) return;
    int c  = idx % ML;
    int bz = idx / ML;
    const float* p = g_a2 + (long long)bz*ML*ML + c;
    float s = 0.f;
    for (int r2=0;r2<ML;r2++) s += fabsf(p[(long long)r2*ML]);
    atomicMax(&g_red[0], __float_as_int(s));
}
__global__ void rowsum_kernel(){
    int idx = blockIdx.x*blockDim.x + threadIdx.x;   // BH*ML
    if (idx >= BH*ML) return;
    int r2 = idx % ML;
    int bz = idx / ML;
    const float* p = g_a2 + (long long)bz*ML*ML + (long long)r2*ML;
    float s = 0.f;
    for (int c=0;c<ML;c++) s += fabsf(p[c]);
    atomicMax(&g_red[1], __float_as_int(s));
}
__global__ void zinit_kernel(){
    long long idx = (long long)blockIdx.x*blockDim.x + threadIdx.x;
    if (idx >= (long long)BH*ML*ML) return;
    int j = (int)(idx % ML);
    long long r = idx / ML;
    int i  = (int)(r % ML);
    int bz = (int)(r / ML);
    float c = __int_as_float(g_red[0]) * __int_as_float(g_red[1]);
    g_zb[idx] = g_a2[((long long)bz*ML + j)*ML + i] / c;
}

// T = a*I - P
__global__ void aimx_kernel(float a, const float* __restrict__ P, float* __restrict__ T){
    long long idx = (long long)blockIdx.x*blockDim.x + threadIdx.x;
    if (idx >= (long long)BH*ML*ML) return;
    int j = (int)(idx % ML);
    int i = (int)((idx / ML) % ML);
    T[idx] = (i==j ? a : 0.f) - P[idx];
}

// y[b,n,h*64+d] = ao[b,h,n,d] + depthwise_conv(v)[b,h,n,d]
__global__ void combine_kernel(const float* __restrict__ cw){
    long long idx = (long long)blockIdx.x*blockDim.x + threadIdx.x;
    if (idx >= (long long)BH*NPAD*DHD) return;
    int d = (int)(idx & 63);
    long long r = idx >> 6;
    int n  = (int)(r % NPAD);
    int bh = (int)(r / NPAD);
    int h  = bh % NH, b = bh / NH;
    float s = g_ao[idx];
    const float* w  = cw + h*KC;
    const float* vp = g_v + ((long long)bh*NPAD)*DHD + d;
    int k0 = (16-n > 0) ? (16-n) : 0;
    int k1 = (NPAD+16-n < KC) ? (NPAD+16-n) : KC;
    for (int kk=k0; kk<k1; kk++)
        s = fmaf(vp[(long long)(n+kk-16)*DHD], w[kk], s);
    g_y[((long long)b*NPAD + n)*DMODEL + h*DHD + d] = s;
}

__global__ void final_kernel(const float* __restrict__ fw,
                             const float* __restrict__ fb,
                             float* __restrict__ out){
    __shared__ float sh[8];
    int b = blockIdx.x;
    int t = threadIdx.x;  // 256
    const float* hp = g_h + (long long)b*LSEQ*DMODEL;
    float s = 0.f;
    for (long long i=t; i<(long long)LSEQ*DMODEL; i+=256)
        s = fmaf(hp[i], fw[i], s);
    s = blockSumN(s, sh, 8);
    if (t==0) out[b] = s + fb[0];
}

// ---------------- host-side GEMM dispatch ----------------
static void run_gemm(int tb, int epi, int Mi, int Ni, int Ki,
                     const float* A, int lda, long long sA,
                     const float* Bm, int ldb, long long sB,
                     float* C, int ldc, long long sC,
                     int batch, float alpha, const float* bias)
{
    if (tb == 0 && (Mi % 128) == 0 && (Ni % 128) == 0 && (Ki % 8) == 0) {
        dim3 g(Ni/128, Mi/128, batch), t(256);
        if      (epi==0) gemm128_kernel<0><<<g,t>>>(Ki,A,lda,sA,Bm,ldb,sB,C,ldc,sC,alpha,bias);
        else if (epi==2) gemm128_kernel<2><<<g,t>>>(Ki,A,lda,sA,Bm,ldb,sB,C,ldc,sC,alpha,bias);
        else if (epi==3) gemm128_kernel<3><<<g,t>>>(Ki,A,lda,sA,Bm,ldb,sB,C,ldc,sC,alpha,bias);
        else             gemm128_kernel<4><<<g,t>>>(Ki,A,lda,sA,Bm,ldb,sB,C,ldc,sC,alpha,bias);
        return;
    }
    dim3 g(Ni/64, Mi/64, batch), t(256);
    if (tb==0){
        if      (epi==0) gemm_kernel<0,0><<<g,t>>>(Ki,A,lda,sA,Bm,ldb,sB,C,ldc,sC,alpha,bias);
        else if (epi==2) gemm_kernel<0,2><<<g,t>>>(Ki,A,lda,sA,Bm,ldb,sB,C,ldc,sC,alpha,bias);
        else if (epi==3) gemm_kernel<0,3><<<g,t>>>(Ki,A,lda,sA,Bm,ldb,sB,C,ldc,sC,alpha,bias);
        else             gemm_kernel<0,4><<<g,t>>>(Ki,A,lda,sA,Bm,ldb,sB,C,ldc,sC,alpha,bias);
    } else {
        gemm_kernel<1,0><<<g,t>>>(Ki,A,lda,sA,Bm,ldb,sB,C,ldc,sC,alpha,bias);
    }
}

extern "C" void kernel_launch(void* const* d_in, const int* in_sizes, int n_in,
                              void* d_out, int out_size)
{
    (void)in_sizes; (void)n_in; (void)out_size;
    const int*   x       = (const int*)  d_in[0];
    const float* enc_emb = (const float*)d_in[1];
    const float* pos_emb = (const float*)d_in[2];
    const float* ln1_s   = (const float*)d_in[3];
    const float* ln1_b   = (const float*)d_in[4];
    const float* qkv_w   = (const float*)d_in[5];
    const float* aout_w  = (const float*)d_in[6];
    const float* aout_b  = (const float*)d_in[7];
    const float* conv_k  = (const float*)d_in[8];
    const float* ln2_s   = (const float*)d_in[9];
    const float* ln2_b   = (const float*)d_in[10];
    const float* ff_w1   = (const float*)d_in[11];
    const float* ff_b1   = (const float*)d_in[12];
    const float* ff_w2   = (const float*)d_in[13];
    const float* ff_b2   = (const float*)d_in[14];
    const float* fin_w   = (const float*)d_in[15];
    const float* fin_b   = (const float*)d_in[16];
    float* out = (float*)d_out;

    float *p_h,*p_x,*p_qkv,*p_q,*p_k,*p_v,*p_ql,*p_kl,*p_a1,*p_a3,*p_a2;
    float *p_z,*p_z2,*p_p,*p_t,*p_t2,*p_kv,*p_a1z,*p_ao,*p_y,*p_x2,*p_ff;
    cudaGetSymbolAddress((void**)&p_h,  g_h);
    cudaGetSymbolAddress((void**)&p_x,  g_x);
    cudaGetSymbolAddress((void**)&p_qkv,g_qkv);
    cudaGetSymbolAddress((void**)&p_q,  g_q);
    cudaGetSymbolAddress((void**)&p_k,  g_k);
    cudaGetSymbolAddress((void**)&p_v,  g_v);
    cudaGetSymbolAddress((void**)&p_ql, g_ql);
    cudaGetSymbolAddress((void**)&p_kl, g_kl);
    cudaGetSymbolAddress((void**)&p_a1, g_a1);
    cudaGetSymbolAddress((void**)&p_a3, g_a3);
    cudaGetSymbolAddress((void**)&p_a2, g_a2);
    cudaGetSymbolAddress((void**)&p_z,  g_zb);
    cudaGetSymbolAddress((void**)&p_z2, g_zb2);
    cudaGetSymbolAddress((void**)&p_p,  g_pb);
    cudaGetSymbolAddress((void**)&p_t,  g_tb);
    cudaGetSymbolAddress((void**)&p_t2, g_tb2);
    cudaGetSymbolAddress((void**)&p_kv, g_kvb);
    cudaGetSymbolAddress((void**)&p_a1z,g_a1z);
    cudaGetSymbolAddress((void**)&p_ao, g_ao);
    cudaGetSymbolAddress((void**)&p_y,  g_y);
    cudaGetSymbolAddress((void**)&p_x2, g_x2);
    cudaGetSymbolAddress((void**)&p_ff, g_ff);

    const long long MM  = (long long)ML*ML;
    const long long NM  = (long long)NPAD*ML;
    const long long ND  = (long long)NPAD*DHD;
    const long long MD  = (long long)ML*DHD;

    {
        long long tot = (long long)BATCH*LSEQ*DMODEL;
        embed_kernel<<<(unsigned)((tot+255)/256),256>>>(x, enc_emb, pos_emb);
        int tot2 = BATCH*PADL*DMODEL;
        zero_pad_kernel<<<(tot2+255)/256,256>>>();
    }

    for (int lay=0; lay<DEPTH; lay++){
        // LN1 -> padded g_x
        ln_kernel<<<BATCH*LSEQ,256>>>(p_h, p_x, ln1_s+(long long)lay*DMODEL, ln1_b+(long long)lay*DMODEL, 1);
        // QKV gemm: (B*N,512) @ (512,1536)
        run_gemm(0,0, BATCH*NPAD, 3*DMODEL, DMODEL,
                 p_x, DMODEL, 0,
                 qkv_w + (long long)lay*DMODEL*3*DMODEL, 3*DMODEL, 0,
                 p_qkv, 3*DMODEL, 0, 1, 1.f, nullptr);
        {
            long long tot = (long long)BH*NPAD*DHD;
            qkv_split_kernel<<<(unsigned)((tot+255)/256),256>>>();
            long long tot2 = (long long)BH*ML*DHD;
            landmark_kernel<<<(unsigned)((tot2+255)/256),256>>>();
        }
        // attn1 = softmax(q @ kl^T): 1024x256, K=64, batched 128
        run_gemm(1,0, NPAD, ML, DHD, p_q, DHD, ND, p_kl, DHD, MD, p_a1, ML, NM, BH, 1.f, nullptr);
        softmax_kernel<<<BH*NPAD,128>>>(p_a1, ML);
        // attn2 = softmax(ql @ kl^T): 256x256
        run_gemm(1,0, ML, ML, DHD, p_ql, DHD, MD, p_kl, DHD, MD, p_a2, ML, MM, BH, 1.f, nullptr);
        softmax_kernel<<<BH*ML,128>>>(p_a2, ML);
        // attn3 = softmax(ql @ k^T): 256x1024
        run_gemm(1,0, ML, NPAD, DHD, p_ql, DHD, MD, p_k, DHD, ND, p_a3, NPAD, (long long)ML*NPAD, BH, 1.f, nullptr);
        softmax_kernel<<<BH*ML,128>>>(p_a3, NPAD);

        // ---- Moore-Penrose pinv of attn2 ----
        red_init_kernel<<<1,1>>>();
        colsum_kernel<<<(BH*ML+255)/256,256>>>();
        rowsum_kernel<<<(BH*ML+255)/256,256>>>();
        {
            long long tot = (long long)BH*ML*ML;
            unsigned g = (unsigned)((tot+255)/256);
            zinit_kernel<<<g,256>>>();
        }
        float* zc = p_z; float* zn = p_z2;
        long long totMM = (long long)BH*ML*ML;
        unsigned gMM = (unsigned)((totMM+255)/256);
        for (int it=0; it<6; it++){
            run_gemm(0,0, ML, ML, ML, p_a2, ML, MM, zc, ML, MM, p_p, ML, MM, BH, 1.f, nullptr);
            aimx_kernel<<<gMM,256>>>(7.f, p_p, p_t);
            run_gemm(0,0, ML, ML, ML, p_p, ML, MM, p_t, ML, MM, p_t2, ML, MM, BH, 1.f, nullptr);
            aimx_kernel<<<gMM,256>>>(15.f, p_t2, p_t);
            run_gemm(0,0, ML, ML, ML, p_p, ML, MM, p_t, ML, MM, p_t2, ML, MM, BH, 1.f, nullptr);
            aimx_kernel<<<gMM,256>>>(13.f, p_t2, p_t);
            run_gemm(0,0, ML, ML, ML, zc, ML, MM, p_t, ML, MM, zn, ML, MM, BH, 0.25f, nullptr);
            float* tmp = zc; zc = zn; zn = tmp;
        }

        // kv = attn3 @ v : 256x64, K=1024
        run_gemm(0,0, ML, DHD, NPAD, p_a3, NPAD, (long long)ML*NPAD, p_v, DHD, ND, p_kv, DHD, MD, BH, 1.f, nullptr);
        // a1z = attn1 @ Z : 1024x256, K=256
        run_gemm(0,0, NPAD, ML, ML, p_a1, ML, NM, zc, ML, MM, p_a1z, ML, NM, BH, 1.f, nullptr);
        // ao = a1z @ kv : 1024x64, K=256
        run_gemm(0,0, NPAD, DHD, ML, p_a1z, ML, NM, p_kv, DHD, MD, p_ao, DHD, ND, BH, 1.f, nullptr);
        // combine attn out + depthwise conv(v), transpose to (B,N,D)
        {
            long long tot = (long long)BH*NPAD*DHD;
            combine_kernel<<<(unsigned)((tot+255)/256),256>>>(conv_k + (long long)lay*NH*KC);
        }
        // out projection + residual into h (pad-sliced)
        run_gemm(0,4, BATCH*NPAD, DMODEL, DMODEL,
                 p_y, DMODEL, 0,
                 aout_w + (long long)lay*DMODEL*DMODEL, DMODEL, 0,
                 p_h, DMODEL, 0, 1, 1.f, aout_b + (long long)lay*DMODEL);

        // ---- FFN ----
        ln_kernel<<<BATCH*LSEQ,256>>>(p_h, p_x2, ln2_s+(long long)lay*DMODEL, ln2_b+(long long)lay*DMODEL, 0);
        run_gemm(0,2, BATCH*LSEQ, FFD, DMODEL,
                 p_x2, DMODEL, 0,
                 ff_w1 + (long long)lay*DMODEL*FFD, FFD, 0,
                 p_ff, FFD, 0, 1, 1.f, ff_b1 + (long long)lay*FFD);
        run_gemm(0,3, BATCH*LSEQ, DMODEL, FFD,
                 p_ff, FFD, 0,
                 ff_w2 + (long long)lay*FFD*DMODEL, DMODEL, 0,
                 p_h, DMODEL, 0, 1, 1.f, ff_b2 + (long long)lay*DMODEL);
    }

    final_kernel<<<BATCH,256>>>(fin_w, fin_b, out);
}

// round 3
// speedup vs baseline: 2.3993x; 1.6942x over previous
#include <cuda_runtime.h>
#include <math.h>
#include <stdint.h>

// ---------------- model constants ----------------
#define BATCH 16
#define LSEQ  1000
#define DMODEL 512
#define NH    8
#define DHD   64
#define NPAD  1024
#define PADL  24
#define ML    256     // landmarks
#define LMR   4       // NPAD/ML
#define FFD   2048
#define DEPTH 6
#define KC    33
#define QSCALE 0.125f
#define BH (BATCH*NH)

// ---------------- scratch (device globals; no allocation) ----------------
__device__ float g_h   [BATCH*LSEQ*DMODEL];
__device__ float g_x   [BATCH*NPAD*DMODEL];
__device__ float g_qkv [BATCH*NPAD*3*DMODEL];
__device__ float g_q   [BH*NPAD*DHD];
__device__ float g_k   [BH*NPAD*DHD];
__device__ float g_v   [BH*NPAD*DHD];
__device__ float g_ql  [BH*ML*DHD];
__device__ float g_kl  [BH*ML*DHD];
__device__ float g_a1  [BH*NPAD*ML];
__device__ float g_a3  [BH*ML*NPAD];
__device__ float g_a2  [BH*ML*ML];
__device__ float g_zb  [BH*ML*ML];
__device__ float g_zb2 [BH*ML*ML];
__device__ float g_pb  [BH*ML*ML];
__device__ float g_tb  [BH*ML*ML];
__device__ float g_tb2 [BH*ML*ML];
__device__ float g_kvb [BH*ML*DHD];
__device__ float g_a1z [BH*NPAD*ML];
__device__ float g_ao  [BH*NPAD*DHD];
__device__ float g_y   [BATCH*NPAD*DMODEL];
__device__ float g_x2  [BATCH*LSEQ*DMODEL];
__device__ float g_ff  [BATCH*LSEQ*FFD];
__device__ int   g_red [2];

// ---------------- reductions ----------------
__device__ __forceinline__ float warpSum(float v){
    #pragma unroll
    for (int o=16;o;o>>=1) v += __shfl_xor_sync(0xffffffffu, v, o);
    return v;
}
__device__ __forceinline__ float warpMax(float v){
    #pragma unroll
    for (int o=16;o;o>>=1) v = fmaxf(v, __shfl_xor_sync(0xffffffffu, v, o));
    return v;
}
__device__ __forceinline__ float blockSumN(float v, float* sh, int nw){
    int w = threadIdx.x>>5, l = threadIdx.x&31;
    v = warpSum(v);
    if (l==0) sh[w] = v;
    __syncthreads();
    if (w==0){
        float x = (l < nw) ? sh[l] : 0.f;
        x = warpSum(x);
        if (l==0) sh[0] = x;
    }
    __syncthreads();
    float r = sh[0];
    __syncthreads();
    return r;
}
__device__ __forceinline__ float blockMaxN(float v, float* sh, int nw){
    int w = threadIdx.x>>5, l = threadIdx.x&31;
    v = warpMax(v);
    if (l==0) sh[w] = v;
    __syncthreads();
    if (w==0){
        float x = (l < nw) ? sh[l] : -3.4e38f;
        x = warpMax(x);
        if (l==0) sh[0] = x;
    }
    __syncthreads();
    float r = sh[0];
    __syncthreads();
    return r;
}

// ---------------- tf32 helpers ----------------
__device__ __forceinline__ unsigned f2tf(float x){
    unsigned r;
    asm("cvt.rna.tf32.f32 %0, %1;" : "=r"(r) : "f"(x));
    return r;
}
__device__ __forceinline__ uint4 cvt4(float4 v){
    uint4 u;
    u.x = f2tf(v.x); u.y = f2tf(v.y); u.z = f2tf(v.z); u.w = f2tf(v.w);
    return u;
}
__device__ __forceinline__ void mma_tf32(float c[4],
    unsigned a0, unsigned a1, unsigned a2, unsigned a3,
    unsigned b0, unsigned b1)
{
    asm volatile(
        "mma.sync.aligned.m16n8k8.row.col.f32.tf32.tf32.f32 "
        "{%0,%1,%2,%3}, {%4,%5,%6,%7}, {%8,%9}, {%0,%1,%2,%3};"
        : "+f"(c[0]), "+f"(c[1]), "+f"(c[2]), "+f"(c[3])
        : "r"(a0), "r"(a1), "r"(a2), "r"(a3), "r"(b0), "r"(b1));
}

// epilogue: writes 2 consecutive cols at (r, cc)
// EPI 0: C = alpha*val
// EPI 2: C = gelu(val + bias[c])
// EPI 3: C += val + bias[c]
// EPI 4: pad-sliced residual add into h
// EPI 5: C = alpha*I - val
// EPI 6: C = val ; C2 = alpha*I - val
template<int EPI>
__device__ __forceinline__ void store2(
    float* __restrict__ C, float* __restrict__ C2, int ldc,
    int r, int cc, float v0, float v1,
    float alpha, const float* __restrict__ bias)
{
    if (EPI==0){
        float2 o = {alpha*v0, alpha*v1};
        *(float2*)&C[(long long)r*ldc + cc] = o;
    } else if (EPI==2){
        float x0 = v0 + bias[cc], x1 = v1 + bias[cc+1];
        float2 o;
        o.x = 0.5f*x0*(1.f+erff(x0*0.70710678118654752f));
        o.y = 0.5f*x1*(1.f+erff(x1*0.70710678118654752f));
        *(float2*)&C[(long long)r*ldc + cc] = o;
    } else if (EPI==3){
        float2 o = *(float2*)&C[(long long)r*ldc + cc];
        o.x += v0 + bias[cc];
        o.y += v1 + bias[cc+1];
        *(float2*)&C[(long long)r*ldc + cc] = o;
    } else if (EPI==4){
        int bb = r / NPAD, nl = r % NPAD;
        if (nl >= PADL){
            long long orow = (long long)bb*LSEQ + (nl - PADL);
            float2 o = *(float2*)&C[orow*ldc + cc];
            o.x += v0 + bias[cc];
            o.y += v1 + bias[cc+1];
            *(float2*)&C[orow*ldc + cc] = o;
        }
    } else if (EPI==5){
        float2 o = {(r==cc ? alpha : 0.f) - v0, (r==cc+1 ? alpha : 0.f) - v1};
        *(float2*)&C[(long long)r*ldc + cc] = o;
    } else if (EPI==6){
        float2 o = {v0, v1};
        *(float2*)&C[(long long)r*ldc + cc] = o;
        float2 o2 = {(r==cc ? alpha : 0.f) - v0, (r==cc+1 ? alpha : 0.f) - v1};
        *(float2*)&C2[(long long)r*ldc + cc] = o2;
    }
}

// ============ TF32 tensor-core GEMM: CTA 128x256, warp 64x64 ===============
// C[bz] (M x N) = A[bz](MxK rm) @ B[bz](KxN rm), fp32 accumulate.
// Requires M%128==0, N%256==0, K%8==0.
template<int EPI>
__global__ void __launch_bounds__(256,1) gemm_tf32_kernel(
    int Ki,
    const float* __restrict__ A, int lda, long long sA,
    const float* __restrict__ Bm, int ldb, long long sB,
    float* __restrict__ C, int ldc, long long sC,
    float alpha, const float* __restrict__ bias, float* __restrict__ C2)
{
    __shared__ unsigned As[2][128*12];   // [r][k] stride 12 (bank-safe)
    __shared__ unsigned Bs[2][8*264];    // [k][n] stride 264 (bank-safe)

    const int bz = blockIdx.z;
    A  += (long long)bz*sA;
    Bm += (long long)bz*sB;
    C  += (long long)bz*sC;
    if (EPI==6) C2 += (long long)bz*sC;

    const int row0 = blockIdx.y*128;
    const int col0 = blockIdx.x*256;
    const int tid = threadIdx.x;
    const int warp = tid>>5, lane = tid&31;
    const int wm = warp & 1, wn = warp >> 1;     // 2 x 4 warp grid
    const int g = lane>>2, qc = lane&3;

    // staging maps
    const float* Ag = A + (long long)(row0 + (tid>>1))*lda + ((tid&1)<<2);
    const int s_ar = (tid>>1)*12 + ((tid&1)<<2);
    const int bk0 = tid>>6,       bn0 = (tid&63)<<2;
    const int bk1 = (tid>>6) + 4;
    const float* Bg = Bm + col0;

    float acc[4][8][4];
    #pragma unroll
    for (int mt=0;mt<4;mt++)
        #pragma unroll
        for (int nt=0;nt<8;nt++)
            #pragma unroll
            for (int i=0;i<4;i++) acc[mt][nt][i]=0.f;

    // stage 0
    {
        float4 av  = *(const float4*)Ag;
        float4 b0v = *(const float4*)(Bg + (long long)bk0*ldb + bn0);
        float4 b1v = *(const float4*)(Bg + (long long)bk1*ldb + bn0);
        *(uint4*)&As[0][s_ar]           = cvt4(av);
        *(uint4*)&Bs[0][bk0*264 + bn0]  = cvt4(b0v);
        *(uint4*)&Bs[0][bk1*264 + bn0]  = cvt4(b1v);
    }
    __syncthreads();

    const int nk = Ki >> 3;
    int buf = 0;
    for (int t = 0; t < nk; ++t){
        float4 pa, pb0, pb1;
        if (t+1 < nk){
            pa  = *(const float4*)(Ag + (t+1)*8);
            pb0 = *(const float4*)(Bg + (long long)((t+1)*8 + bk0)*ldb + bn0);
            pb1 = *(const float4*)(Bg + (long long)((t+1)*8 + bk1)*ldb + bn0);
        }

        unsigned af[4][4], bf[8][2];
        const unsigned* Ab = &As[buf][(wm*64 + g)*12 + qc];
        #pragma unroll
        for (int mt=0;mt<4;mt++){
            af[mt][0] = Ab[(mt*16)*12];
            af[mt][1] = Ab[(mt*16+8)*12];
            af[mt][2] = Ab[(mt*16)*12 + 4];
            af[mt][3] = Ab[(mt*16+8)*12 + 4];
        }
        const unsigned* Bb = &Bs[buf][qc*264 + wn*64 + g];
        #pragma unroll
        for (int nt=0;nt<8;nt++){
            bf[nt][0] = Bb[nt*8];
            bf[nt][1] = Bb[4*264 + nt*8];
        }
        #pragma unroll
        for (int mt=0;mt<4;mt++)
            #pragma unroll
            for (int nt=0;nt<8;nt++)
                mma_tf32(acc[mt][nt], af[mt][0],af[mt][1],af[mt][2],af[mt][3],
                         bf[nt][0],bf[nt][1]);

        if (t+1 < nk){
            *(uint4*)&As[buf^1][s_ar]          = cvt4(pa);
            *(uint4*)&Bs[buf^1][bk0*264 + bn0] = cvt4(pb0);
            *(uint4*)&Bs[buf^1][bk1*264 + bn0] = cvt4(pb1);
        }
        __syncthreads();
        buf ^= 1;
    }

    // epilogue
    #pragma unroll
    for (int mt=0;mt<4;mt++){
        int r = row0 + wm*64 + mt*16 + g;
        #pragma unroll
        for (int nt=0;nt<8;nt++){
            int cc = col0 + wn*64 + nt*8 + 2*qc;
            store2<EPI>(C, C2, ldc, r,   cc, acc[mt][nt][0], acc[mt][nt][1], alpha, bias);
            store2<EPI>(C, C2, ldc, r+8, cc, acc[mt][nt][2], acc[mt][nt][3], alpha, bias);
        }
    }
}

// ---------------- generic 64x64 tiled GEMM (small-N / transposed-B) -------
template<int TB, int EPI>
__global__ void __launch_bounds__(256) gemm_kernel(
    int Ki,
    const float* __restrict__ A, int lda, long long sA,
    const float* __restrict__ Bm, int ldb, long long sB,
    float* __restrict__ C, int ldc, long long sC,
    float alpha, const float* __restrict__ bias)
{
    const int bz = blockIdx.z;
    A  += (long long)bz * sA;
    Bm += (long long)bz * sB;
    C  += (long long)bz * sC;
    const int row0 = blockIdx.y * 64;
    const int col0 = blockIdx.x * 64;
    __shared__ float As[16][68];
    __shared__ float Bs[16][68];
    const int tid = threadIdx.x;
    const int ty = tid >> 4, tx = tid & 15;
    const int ar = tid >> 2, akq = (tid & 3) << 2;

    float acc[4][4];
    #pragma unroll
    for (int i=0;i<4;i++)
        #pragma unroll
        for (int j=0;j<4;j++) acc[i][j]=0.f;

    for (int k0 = 0; k0 < Ki; k0 += 16) {
        float4 av = *(const float4*)(A + (long long)(row0+ar)*lda + k0 + akq);
        As[akq+0][ar]=av.x; As[akq+1][ar]=av.y; As[akq+2][ar]=av.z; As[akq+3][ar]=av.w;
        if (TB==0) {
            int bkk = tid >> 4, bc = (tid & 15) << 2;
            float4 bv = *(const float4*)(Bm + (long long)(k0+bkk)*ldb + col0 + bc);
            Bs[bkk][bc+0]=bv.x; Bs[bkk][bc+1]=bv.y; Bs[bkk][bc+2]=bv.z; Bs[bkk][bc+3]=bv.w;
        } else {
            int bc = tid >> 2, bkq = (tid & 3) << 2;
            float4 bv = *(const float4*)(Bm + (long long)(col0+bc)*ldb + k0 + bkq);
            Bs[bkq+0][bc]=bv.x; Bs[bkq+1][bc]=bv.y; Bs[bkq+2][bc]=bv.z; Bs[bkq+3][bc]=bv.w;
        }
        __syncthreads();
        #pragma unroll
        for (int kk=0;kk<16;kk++){
            float a[4], b[4];
            #pragma unroll
            for (int i=0;i<4;i++) a[i]=As[kk][ty+16*i];
            #pragma unroll
            for (int j=0;j<4;j++) b[j]=Bs[kk][tx+16*j];
            #pragma unroll
            for (int i=0;i<4;i++)
                #pragma unroll
                for (int j=0;j<4;j++)
                    acc[i][j] = fmaf(a[i], b[j], acc[i][j]);
        }
        __syncthreads();
    }

    #pragma unroll
    for (int i=0;i<4;i++){
        int r = row0 + ty + 16*i;
        #pragma unroll
        for (int j=0;j<4;j++){
            int c = col0 + tx + 16*j;
            float val = alpha * acc[i][j];
            if (EPI==0) {
                C[(long long)r*ldc + c] = val;
            } else if (EPI==2) {
                float xg = val + bias[c];
                C[(long long)r*ldc + c] = 0.5f*xg*(1.f+erff(xg*0.70710678118654752f));
            } else if (EPI==3) {
                C[(long long)r*ldc + c] += val + bias[c];
            } else if (EPI==4) {
                int bb = r / NPAD, nl = r % NPAD;
                if (nl >= PADL)
                    C[((long long)bb*LSEQ + (nl-PADL))*ldc + c] += val + bias[c];
            }
        }
    }
}

// ---------------- elementwise / small kernels ----------------
__global__ void embed_kernel(const int* __restrict__ x,
                             const float* __restrict__ emb,
                             const float* __restrict__ pos){
    long long idx = (long long)blockIdx.x*blockDim.x + threadIdx.x;
    if (idx >= (long long)BATCH*LSEQ*DMODEL) return;
    int d = (int)(idx % DMODEL);
    long long bl = idx / DMODEL;
    int l = (int)(bl % LSEQ);
    int tok = x[bl];
    g_h[idx] = emb[(long long)tok*DMODEL + d] + pos[(long long)l*DMODEL + d];
}

__global__ void zero_pad_kernel(){
    int idx = blockIdx.x*blockDim.x + threadIdx.x;
    if (idx >= BATCH*PADL*DMODEL) return;
    int d  = idx % DMODEL;
    int bp = idx / DMODEL;
    int b  = bp / PADL, p = bp % PADL;
    g_x[((long long)b*NPAD + p)*DMODEL + d] = 0.f;
}

__global__ void ln_kernel(const float* __restrict__ in, float* __restrict__ out,
                          const float* __restrict__ gm, const float* __restrict__ bt,
                          int padmode){
    __shared__ float sh[8];
    int r = blockIdx.x;
    int t = threadIdx.x;
    const float* p = in + (long long)r*DMODEL;
    float a  = p[t];
    float b2 = p[t+256];
    float s  = blockSumN(a+b2, sh, 8);
    float mu = s * (1.f/512.f);
    float da = a - mu, db = b2 - mu;
    float v  = blockSumN(da*da + db*db, sh, 8) * (1.f/512.f);
    float rstd = rsqrtf(v + 1e-5f);
    long long orow = padmode ? ((long long)(r/LSEQ)*NPAD + PADL + (r%LSEQ)) : (long long)r;
    float* q = out + orow*DMODEL;
    q[t]     = da*rstd*gm[t]     + bt[t];
    q[t+256] = db*rstd*gm[t+256] + bt[t+256];
}

__global__ void qkv_split_kernel(){
    long long idx = (long long)blockIdx.x*blockDim.x + threadIdx.x;
    if (idx >= (long long)BH*NPAD*DHD) return;
    int d = (int)(idx & 63);
    long long r = idx >> 6;
    int n  = (int)(r % NPAD);
    int bh = (int)(r / NPAD);
    int h  = bh % NH, b = bh / NH;
    long long base = ((long long)b*NPAD + n)*(3*DMODEL) + h*DHD + d;
    g_q[idx] = g_qkv[base] * QSCALE;
    g_k[idx] = g_qkv[base + DMODEL];
    g_v[idx] = g_qkv[base + 2*DMODEL];
}

__global__ void landmark_kernel(){
    long long idx = (long long)blockIdx.x*blockDim.x + threadIdx.x;
    if (idx >= (long long)BH*ML*DHD) return;
    int d = (int)(idx & 63);
    long long r = idx >> 6;
    int m  = (int)(r % ML);
    int bh = (int)(r / ML);
    long long base = ((long long)bh*NPAD + (long long)m*LMR)*DHD + d;
    float sq = 0.f, sk = 0.f;
    #pragma unroll
    for (int j=0;j<LMR;j++){ sq += g_q[base + (long long)j*DHD]; sk += g_k[base + (long long)j*DHD]; }
    g_ql[idx] = sq * 0.25f;
    g_kl[idx] = sk * 0.25f;
}

__global__ void softmax_kernel(float* __restrict__ X, int cols){
    __shared__ float sh[4];
    long long row = blockIdx.x;
    float* p = X + row*(long long)cols;
    int t = threadIdx.x;
    int cnt = cols >> 7;
    float v[8];
    float mx = -3.4e38f;
    #pragma unroll
    for (int i=0;i<8;i++) if (i<cnt){ v[i]=p[t + (i<<7)]; mx = fmaxf(mx, v[i]); }
    mx = blockMaxN(mx, sh, 4);
    float s = 0.f;
    #pragma unroll
    for (int i=0;i<8;i++) if (i<cnt){ v[i]=expf(v[i]-mx); s += v[i]; }
    s = blockSumN(s, sh, 4);
    float inv = 1.f/s;
    #pragma unroll
    for (int i=0;i<8;i++) if (i<cnt) p[t + (i<<7)] = v[i]*inv;
}

__global__ void red_init_kernel(){ g_red[0]=0; g_red[1]=0; }

__global__ void colsum_kernel(){
    int idx = blockIdx.x*blockDim.x + threadIdx.x;
    if (idx >= BH*ML) return;
    int c  = idx % ML;
    int bz = idx / ML;
    const float* p = g_a2 + (long long)bz*ML*ML + c;
    float s = 0.f;
    for (int r2=0;r2<ML;r2++) s += fabsf(p[(long long)r2*ML]);
    atomicMax(&g_red[0], __float_as_int(s));
}
__global__ void rowsum_kernel(){
    int idx = blockIdx.x*blockDim.x + threadIdx.x;
    if (idx >= BH*ML) return;
    int r2 = idx % ML;
    int bz = idx / ML;
    const float* p = g_a2 + (long long)bz*ML*ML + (long long)r2*ML;
    float s = 0.f;
    for (int c=0;c<ML;c++) s += fabsf(p[c]);
    atomicMax(&g_red[1], __float_as_int(s));
}
__global__ void zinit_kernel(){
    long long idx = (long long)blockIdx.x*blockDim.x + threadIdx.x;
    if (idx >= (long long)BH*ML*ML) return;
    int j = (int)(idx % ML);
    long long r = idx / ML;
    int i  = (int)(r % ML);
    int bz = (int)(r / ML);
    float c = __int_as_float(g_red[0]) * __int_as_float(g_red[1]);
    g_zb[idx] = g_a2[((long long)bz*ML + j)*ML + i] / c;
}

__global__ void combine_kernel(const float* __restrict__ cw){
    long long idx = (long long)blockIdx.x*blockDim.x + threadIdx.x;
    if (idx >= (long long)BH*NPAD*DHD) return;
    int d = (int)(idx & 63);
    long long r = idx >> 6;
    int n  = (int)(r % NPAD);
    int bh = (int)(r / NPAD);
    int h  = bh % NH, b = bh / NH;
    float s = g_ao[idx];
    const float* w  = cw + h*KC;
    const float* vp = g_v + ((long long)bh*NPAD)*DHD + d;
    int k0 = (16-n > 0) ? (16-n) : 0;
    int k1 = (NPAD+16-n < KC) ? (NPAD+16-n) : KC;
    for (int kk=k0; kk<k1; kk++)
        s = fmaf(vp[(long long)(n+kk-16)*DHD], w[kk], s);
    g_y[((long long)b*NPAD + n)*DMODEL + h*DHD + d] = s;
}

__global__ void final_kernel(const float* __restrict__ fw,
                             const float* __restrict__ fb,
                             float* __restrict__ out){
    __shared__ float sh[8];
    int b = blockIdx.x;
    int t = threadIdx.x;
    const float* hp = g_h + (long long)b*LSEQ*DMODEL;
    float s = 0.f;
    for (long long i=t; i<(long long)LSEQ*DMODEL; i+=256)
        s = fmaf(hp[i], fw[i], s);
    s = blockSumN(s, sh, 8);
    if (t==0) out[b] = s + fb[0];
}

// ---------------- host-side GEMM dispatch ----------------
static void run_gemm(int tb, int epi, int Mi, int Ni, int Ki,
                     const float* A, int lda, long long sA,
                     const float* Bm, int ldb, long long sB,
                     float* C, int ldc, long long sC,
                     int batch, float alpha, const float* bias,
                     float* C2 = nullptr)
{
    if (tb == 0 && (Mi % 128) == 0 && (Ni % 256) == 0 && (Ki % 8) == 0) {
        dim3 g(Ni/256, Mi/128, batch), t(256);
        switch (epi) {
            case 0: gemm_tf32_kernel<0><<<g,t>>>(Ki,A,lda,sA,Bm,ldb,sB,C,ldc,sC,alpha,bias,C2); break;
            case 2: gemm_tf32_kernel<2><<<g,t>>>(Ki,A,lda,sA,Bm,ldb,sB,C,ldc,sC,alpha,bias,C2); break;
            case 3: gemm_tf32_kernel<3><<<g,t>>>(Ki,A,lda,sA,Bm,ldb,sB,C,ldc,sC,alpha,bias,C2); break;
            case 4: gemm_tf32_kernel<4><<<g,t>>>(Ki,A,lda,sA,Bm,ldb,sB,C,ldc,sC,alpha,bias,C2); break;
            case 5: gemm_tf32_kernel<5><<<g,t>>>(Ki,A,lda,sA,Bm,ldb,sB,C,ldc,sC,alpha,bias,C2); break;
            case 6: gemm_tf32_kernel<6><<<g,t>>>(Ki,A,lda,sA,Bm,ldb,sB,C,ldc,sC,alpha,bias,C2); break;
        }
        return;
    }
    dim3 g(Ni/64, Mi/64, batch), t(256);
    if (tb==0){
        if      (epi==0) gemm_kernel<0,0><<<g,t>>>(Ki,A,lda,sA,Bm,ldb,sB,C,ldc,sC,alpha,bias);
        else if (epi==2) gemm_kernel<0,2><<<g,t>>>(Ki,A,lda,sA,Bm,ldb,sB,C,ldc,sC,alpha,bias);
        else if (epi==3) gemm_kernel<0,3><<<g,t>>>(Ki,A,lda,sA,Bm,ldb,sB,C,ldc,sC,alpha,bias);
        else             gemm_kernel<0,4><<<g,t>>>(Ki,A,lda,sA,Bm,ldb,sB,C,ldc,sC,alpha,bias);
    } else {
        gemm_kernel<1,0><<<g,t>>>(Ki,A,lda,sA,Bm,ldb,sB,C,ldc,sC,alpha,bias);
    }
}

extern "C" void kernel_launch(void* const* d_in, const int* in_sizes, int n_in,
                              void* d_out, int out_size)
{
    (void)in_sizes; (void)n_in; (void)out_size;
    const int*   x       = (const int*)  d_in[0];
    const float* enc_emb = (const float*)d_in[1];
    const float* pos_emb = (const float*)d_in[2];
    const float* ln1_s   = (const float*)d_in[3];
    const float* ln1_b   = (const float*)d_in[4];
    const float* qkv_w   = (const float*)d_in[5];
    const float* aout_w  = (const float*)d_in[6];
    const float* aout_b  = (const float*)d_in[7];
    const float* conv_k  = (const float*)d_in[8];
    const float* ln2_s   = (const float*)d_in[9];
    const float* ln2_b   = (const float*)d_in[10];
    const float* ff_w1   = (const float*)d_in[11];
    const float* ff_b1   = (const float*)d_in[12];
    const float* ff_w2   = (const float*)d_in[13];
    const float* ff_b2   = (const float*)d_in[14];
    const float* fin_w   = (const float*)d_in[15];
    const float* fin_b   = (const float*)d_in[16];
    float* out = (float*)d_out;

    float *p_h,*p_x,*p_qkv,*p_q,*p_k,*p_v,*p_ql,*p_kl,*p_a1,*p_a3,*p_a2;
    float *p_z,*p_z2,*p_p,*p_t,*p_t2,*p_kv,*p_a1z,*p_ao,*p_y,*p_x2,*p_ff;
    cudaGetSymbolAddress((void**)&p_h,  g_h);
    cudaGetSymbolAddress((void**)&p_x,  g_x);
    cudaGetSymbolAddress((void**)&p_qkv,g_qkv);
    cudaGetSymbolAddress((void**)&p_q,  g_q);
    cudaGetSymbolAddress((void**)&p_k,  g_k);
    cudaGetSymbolAddress((void**)&p_v,  g_v);
    cudaGetSymbolAddress((void**)&p_ql, g_ql);
    cudaGetSymbolAddress((void**)&p_kl, g_kl);
    cudaGetSymbolAddress((void**)&p_a1, g_a1);
    cudaGetSymbolAddress((void**)&p_a3, g_a3);
    cudaGetSymbolAddress((void**)&p_a2, g_a2);
    cudaGetSymbolAddress((void**)&p_z,  g_zb);
    cudaGetSymbolAddress((void**)&p_z2, g_zb2);
    cudaGetSymbolAddress((void**)&p_p,  g_pb);
    cudaGetSymbolAddress((void**)&p_t,  g_tb);
    cudaGetSymbolAddress((void**)&p_t2, g_tb2);
    cudaGetSymbolAddress((void**)&p_kv, g_kvb);
    cudaGetSymbolAddress((void**)&p_a1z,g_a1z);
    cudaGetSymbolAddress((void**)&p_ao, g_ao);
    cudaGetSymbolAddress((void**)&p_y,  g_y);
    cudaGetSymbolAddress((void**)&p_x2, g_x2);
    cudaGetSymbolAddress((void**)&p_ff, g_ff);

    const long long MM  = (long long)ML*ML;
    const long long NM  = (long long)NPAD*ML;
    const long long ND  = (long long)NPAD*DHD;
    const long long MD  = (long long)ML*DHD;

    {
        long long tot = (long long)BATCH*LSEQ*DMODEL;
        embed_kernel<<<(unsigned)((tot+255)/256),256>>>(x, enc_emb, pos_emb);
        int tot2 = BATCH*PADL*DMODEL;
        zero_pad_kernel<<<(tot2+255)/256,256>>>();
    }

    for (int lay=0; lay<DEPTH; lay++){
        // LN1 -> padded g_x
        ln_kernel<<<BATCH*LSEQ,256>>>(p_h, p_x, ln1_s+(long long)lay*DMODEL, ln1_b+(long long)lay*DMODEL, 1);
        // QKV gemm: (B*N,512) @ (512,1536)  [tensor]
        run_gemm(0,0, BATCH*NPAD, 3*DMODEL, DMODEL,
                 p_x, DMODEL, 0,
                 qkv_w + (long long)lay*DMODEL*3*DMODEL, 3*DMODEL, 0,
                 p_qkv, 3*DMODEL, 0, 1, 1.f, nullptr);
        {
            long long tot = (long long)BH*NPAD*DHD;
            qkv_split_kernel<<<(unsigned)((tot+255)/256),256>>>();
            long long tot2 = (long long)BH*ML*DHD;
            landmark_kernel<<<(unsigned)((tot2+255)/256),256>>>();
        }
        // attn1 = softmax(q @ kl^T)
        run_gemm(1,0, NPAD, ML, DHD, p_q, DHD, ND, p_kl, DHD, MD, p_a1, ML, NM, BH, 1.f, nullptr);
        softmax_kernel<<<BH*NPAD,128>>>(p_a1, ML);
        // attn2 = softmax(ql @ kl^T)
        run_gemm(1,0, ML, ML, DHD, p_ql, DHD, MD, p_kl, DHD, MD, p_a2, ML, MM, BH, 1.f, nullptr);
        softmax_kernel<<<BH*ML,128>>>(p_a2, ML);
        // attn3 = softmax(ql @ k^T)
        run_gemm(1,0, ML, NPAD, DHD, p_ql, DHD, MD, p_k, DHD, ND, p_a3, NPAD, (long long)ML*NPAD, BH, 1.f, nullptr);
        softmax_kernel<<<BH*ML,128>>>(p_a3, NPAD);

        // ---- Moore-Penrose pinv of attn2 (tensor GEMMs, fused aI-X epilogues) ----
        red_init_kernel<<<1,1>>>();
        colsum_kernel<<<(BH*ML+255)/256,256>>>();
        rowsum_kernel<<<(BH*ML+255)/256,256>>>();
        {
            long long tot = (long long)BH*ML*ML;
            unsigned g = (unsigned)((tot+255)/256);
            zinit_kernel<<<g,256>>>();
        }
        float* zc = p_z; float* zn = p_z2;
        for (int it=0; it<6; it++){
            // P = A2@Z ; T = 7I - P
            run_gemm(0,6, ML, ML, ML, p_a2, ML, MM, zc, ML, MM, p_p, ML, MM, BH, 7.f, nullptr, p_t);
            // T2 = 15I - P@T
            run_gemm(0,5, ML, ML, ML, p_p, ML, MM, p_t, ML, MM, p_t2, ML, MM, BH, 15.f, nullptr);
            // T = 13I - P@T2
            run_gemm(0,5, ML, ML, ML, p_p, ML, MM, p_t2, ML, MM, p_t, ML, MM, BH, 13.f, nullptr);
            // Zn = 0.25 * Z@T
            run_gemm(0,0, ML, ML, ML, zc, ML, MM, p_t, ML, MM, zn, ML, MM, BH, 0.25f, nullptr);
            float* tmp = zc; zc = zn; zn = tmp;
        }

        // kv = attn3 @ v : 256x64, K=1024  [SIMT small-N]
        run_gemm(0,0, ML, DHD, NPAD, p_a3, NPAD, (long long)ML*NPAD, p_v, DHD, ND, p_kv, DHD, MD, BH, 1.f, nullptr);
        // a1z = attn1 @ Z : 1024x256, K=256  [tensor]
        run_gemm(0,0, NPAD, ML, ML, p_a1, ML, NM, zc, ML, MM, p_a1z, ML, NM, BH, 1.f, nullptr);
        // ao = a1z @ kv : 1024x64, K=256  [SIMT small-N]
        run_gemm(0,0, NPAD, DHD, ML, p_a1z, ML, NM, p_kv, DHD, MD, p_ao, DHD, ND, BH, 1.f, nullptr);
        {
            long long tot = (long long)BH*NPAD*DHD;
            combine_kernel<<<(unsigned)((tot+255)/256),256>>>(conv_k + (long long)lay*NH*KC);
        }
        // out projection + residual into h (pad-sliced)  [tensor]
        run_gemm(0,4, BATCH*NPAD, DMODEL, DMODEL,
                 p_y, DMODEL, 0,
                 aout_w + (long long)lay*DMODEL*DMODEL, DMODEL, 0,
                 p_h, DMODEL, 0, 1, 1.f, aout_b + (long long)lay*DMODEL);

        // ---- FFN ----
        ln_kernel<<<BATCH*LSEQ,256>>>(p_h, p_x2, ln2_s+(long long)lay*DMODEL, ln2_b+(long long)lay*DMODEL, 0);
        run_gemm(0,2, BATCH*LSEQ, FFD, DMODEL,
                 p_x2, DMODEL, 0,
                 ff_w1 + (long long)lay*DMODEL*FFD, FFD, 0,
                 p_ff, FFD, 0, 1, 1.f, ff_b1 + (long long)lay*FFD);
        run_gemm(0,3, BATCH*LSEQ, DMODEL, FFD,
                 p_ff, FFD, 0,
                 ff_w2 + (long long)lay*FFD*DMODEL, DMODEL, 0,
                 p_h, DMODEL, 0, 1, 1.f, ff_b2 + (long long)lay*DMODEL);
    }

    final_kernel<<<BATCH,256>>>(fin_w, fin_b, out);
}

// round 4
// speedup vs baseline: 2.8935x; 1.2060x over previous
#include <cuda_runtime.h>
#include <math.h>
#include <stdint.h>

// ---------------- model constants ----------------
#define BATCH 16
#define LSEQ  1000
#define DMODEL 512
#define NH    8
#define DHD   64
#define NPAD  1024
#define PADL  24
#define ML    256
#define LMR   4
#define FFD   2048
#define DEPTH 6
#define KC    33
#define QSCALE 0.125f
#define BH (BATCH*NH)

// ---------------- scratch ----------------
__device__ float g_h   [BATCH*LSEQ*DMODEL];
__device__ float g_x   [BATCH*NPAD*DMODEL];
__device__ float g_qkv [BATCH*NPAD*3*DMODEL];
__device__ float g_q   [BH*NPAD*DHD];
__device__ float g_k   [BH*NPAD*DHD];
__device__ float g_v   [BH*NPAD*DHD];
__device__ float g_ql  [BH*ML*DHD];
__device__ float g_kl  [BH*ML*DHD];
__device__ float g_a1  [BH*NPAD*ML];
__device__ float g_a3  [BH*ML*NPAD];
__device__ float g_a2  [BH*ML*ML];
__device__ float g_zb  [BH*ML*ML];
__device__ float g_zb2 [BH*ML*ML];
__device__ float g_pb  [BH*ML*ML];
__device__ float g_tb  [BH*ML*ML];
__device__ float g_tb2 [BH*ML*ML];
__device__ float g_kvb [BH*ML*DHD];
__device__ float g_a1z [BH*NPAD*ML];
__device__ float g_ao  [BH*NPAD*DHD];
__device__ float g_y   [BATCH*NPAD*DMODEL];
__device__ float g_x2  [BATCH*LSEQ*DMODEL];
__device__ float g_ff  [BATCH*LSEQ*FFD];
__device__ int   g_red [2];

// ---------------- reductions ----------------
__device__ __forceinline__ float warpSum(float v){
    #pragma unroll
    for (int o=16;o;o>>=1) v += __shfl_xor_sync(0xffffffffu, v, o);
    return v;
}
__device__ __forceinline__ float warpMax(float v){
    #pragma unroll
    for (int o=16;o;o>>=1) v = fmaxf(v, __shfl_xor_sync(0xffffffffu, v, o));
    return v;
}
__device__ __forceinline__ float blockSumN(float v, float* sh, int nw){
    int w = threadIdx.x>>5, l = threadIdx.x&31;
    v = warpSum(v);
    if (l==0) sh[w] = v;
    __syncthreads();
    if (w==0){
        float x = (l < nw) ? sh[l] : 0.f;
        x = warpSum(x);
        if (l==0) sh[0] = x;
    }
    __syncthreads();
    float r = sh[0];
    __syncthreads();
    return r;
}
__device__ __forceinline__ float blockMaxN(float v, float* sh, int nw){
    int w = threadIdx.x>>5, l = threadIdx.x&31;
    v = warpMax(v);
    if (l==0) sh[w] = v;
    __syncthreads();
    if (w==0){
        float x = (l < nw) ? sh[l] : -3.4e38f;
        x = warpMax(x);
        if (l==0) sh[0] = x;
    }
    __syncthreads();
    float r = sh[0];
    __syncthreads();
    return r;
}

// ---------------- tf32 helpers ----------------
__device__ __forceinline__ unsigned f2tf(float x){
    unsigned r;
    asm("cvt.rna.tf32.f32 %0, %1;" : "=r"(r) : "f"(x));
    return r;
}
__device__ __forceinline__ uint4 cvt4(float4 v){
    uint4 u;
    u.x = f2tf(v.x); u.y = f2tf(v.y); u.z = f2tf(v.z); u.w = f2tf(v.w);
    return u;
}
__device__ __forceinline__ void mma_tf32(float c[4],
    unsigned a0, unsigned a1, unsigned a2, unsigned a3,
    unsigned b0, unsigned b1)
{
    asm volatile(
        "mma.sync.aligned.m16n8k8.row.col.f32.tf32.tf32.f32 "
        "{%0,%1,%2,%3}, {%4,%5,%6,%7}, {%8,%9}, {%0,%1,%2,%3};"
        : "+f"(c[0]), "+f"(c[1]), "+f"(c[2]), "+f"(c[3])
        : "r"(a0), "r"(a1), "r"(a2), "r"(a3), "r"(b0), "r"(b1));
}

// epilogue: writes 2 consecutive cols at (r, cc)
template<int EPI>
__device__ __forceinline__ void store2(
    float* __restrict__ C, float* __restrict__ C2, int ldc,
    int r, int cc, float v0, float v1,
    float alpha, const float* __restrict__ bias)
{
    if (EPI==0){
        float2 o = {alpha*v0, alpha*v1};
        *(float2*)&C[(long long)r*ldc + cc] = o;
    } else if (EPI==2){
        float x0 = v0 + bias[cc], x1 = v1 + bias[cc+1];
        float2 o;
        o.x = 0.5f*x0*(1.f+erff(x0*0.70710678118654752f));
        o.y = 0.5f*x1*(1.f+erff(x1*0.70710678118654752f));
        *(float2*)&C[(long long)r*ldc + cc] = o;
    } else if (EPI==3){
        float2 o = *(float2*)&C[(long long)r*ldc + cc];
        o.x += v0 + bias[cc];
        o.y += v1 + bias[cc+1];
        *(float2*)&C[(long long)r*ldc + cc] = o;
    } else if (EPI==4){
        int bb = r / NPAD, nl = r % NPAD;
        if (nl >= PADL){
            long long orow = (long long)bb*LSEQ + (nl - PADL);
            float2 o = *(float2*)&C[orow*ldc + cc];
            o.x += v0 + bias[cc];
            o.y += v1 + bias[cc+1];
            *(float2*)&C[orow*ldc + cc] = o;
        }
    } else if (EPI==5){
        float2 o = {(r==cc ? alpha : 0.f) - v0, (r==cc+1 ? alpha : 0.f) - v1};
        *(float2*)&C[(long long)r*ldc + cc] = o;
    } else if (EPI==6){
        float2 o = {v0, v1};
        *(float2*)&C[(long long)r*ldc + cc] = o;
        float2 o2 = {(r==cc ? alpha : 0.f) - v0, (r==cc+1 ? alpha : 0.f) - v1};
        *(float2*)&C2[(long long)r*ldc + cc] = o2;
    }
}

// ============ TF32 tensor GEMM v2: CTA 128x256, K-tile 16, pipelined =======
// TB=0: B is KxN rm.  TB=1: B is NxK rm (C = A @ B^T).
// Requires M%128==0, N%256==0, K%16==0.
#define AS_STRIDE 20
#define AS_HALF   (128*AS_STRIDE)
#define BS0_STRIDE 264
#define BS0_HALF  (16*BS0_STRIDE)
#define BS1_STRIDE 20
#define BS1_HALF  (256*BS1_STRIDE)
#define SMEM_TC_BYTES ((2*AS_HALF + 2*BS1_HALF)*4)   // 61440 (max of TB0/TB1)

template<int TB, int EPI>
__global__ void __launch_bounds__(256,1) gemm_tc_kernel(
    int Ki,
    const float* __restrict__ A, int lda, long long sA,
    const float* __restrict__ Bm, int ldb, long long sB,
    float* __restrict__ C, int ldc, long long sC,
    float alpha, const float* __restrict__ bias, float* __restrict__ C2)
{
    extern __shared__ unsigned sm[];
    unsigned* As = sm;
    unsigned* Bs = sm + 2*AS_HALF;

    const int bz = blockIdx.z;
    A  += (long long)bz*sA;
    Bm += (long long)bz*sB;
    C  += (long long)bz*sC;
    if (EPI==6) C2 += (long long)bz*sC;

    const int row0 = blockIdx.y*128;
    const int col0 = blockIdx.x*256;
    const int tid = threadIdx.x;
    const int warp = tid>>5, lane = tid&31;
    const int wm = warp & 1, wn = warp >> 1;   // 2 x 4 warp grid, warp tile 64x64
    const int g = lane>>2, qc = lane&3;

    // --- staging maps ---
    // A: 128 rows x 16 k = 512 float4; 2 per thread (rows r and r+64)
    const int a_r = tid>>2;
    const int a_kc = (tid&3)<<2;
    // B TB0: 16 k x 256 n = 1024 float4; 4 per thread
    const int b0_k = tid>>6;
    const int b0_n = (tid&63)<<2;
    // B TB1: 256 n x 16 k = 1024 float4; 4 per thread (n, n+64, n+128, n+192)
    const int b1_n = tid>>2;
    const int b1_kc = (tid&3)<<2;

    float acc[4][8][4];
    #pragma unroll
    for (int mt=0;mt<4;mt++)
        #pragma unroll
        for (int nt=0;nt<8;nt++)
            #pragma unroll
            for (int i=0;i<4;i++) acc[mt][nt][i]=0.f;

    float4 pA[2], pB[4];
    // ---- initial stage: kt = 0 ----
    #pragma unroll
    for (int i=0;i<2;i++)
        pA[i] = *(const float4*)(A + (long long)(row0 + a_r + i*64)*lda + a_kc);
    if (TB==0){
        #pragma unroll
        for (int i=0;i<4;i++)
            pB[i] = *(const float4*)(Bm + (long long)(b0_k + i*4)*ldb + col0 + b0_n);
    } else {
        #pragma unroll
        for (int i=0;i<4;i++)
            pB[i] = *(const float4*)(Bm + (long long)(col0 + b1_n + i*64)*ldb + b1_kc);
    }
    #pragma unroll
    for (int i=0;i<2;i++)
        *(uint4*)&As[(a_r + i*64)*AS_STRIDE + a_kc] = cvt4(pA[i]);
    if (TB==0){
        #pragma unroll
        for (int i=0;i<4;i++)
            *(uint4*)&Bs[(b0_k + i*4)*BS0_STRIDE + b0_n] = cvt4(pB[i]);
    } else {
        #pragma unroll
        for (int i=0;i<4;i++)
            *(uint4*)&Bs[(b1_n + i*64)*BS1_STRIDE + b1_kc] = cvt4(pB[i]);
    }
    __syncthreads();

    // fragment bases (offsets within a buffer)
    const int a_frag_off = (wm*64 + g)*AS_STRIDE + qc;
    const int b0_frag_off = qc*BS0_STRIDE + wn*64 + g;
    const int b1_frag_off = (wn*64 + g)*BS1_STRIDE + qc;

    unsigned af0[4][4], bf0[8][2], af1[4][4], bf1[8][2];

    // load frag group0 (ks=0) from buffer 0
    {
        const unsigned* Ab = As + a_frag_off;
        #pragma unroll
        for (int mt=0;mt<4;mt++){
            const unsigned* p = Ab + (mt*16)*AS_STRIDE;
            af0[mt][0] = p[0];
            af0[mt][1] = p[8*AS_STRIDE];
            af0[mt][2] = p[4];
            af0[mt][3] = p[8*AS_STRIDE+4];
        }
        if (TB==0){
            const unsigned* Bb = Bs + b0_frag_off;
            #pragma unroll
            for (int nt=0;nt<8;nt++){
                bf0[nt][0] = Bb[nt*8];
                bf0[nt][1] = Bb[4*BS0_STRIDE + nt*8];
            }
        } else {
            const unsigned* Bb = Bs + b1_frag_off;
            #pragma unroll
            for (int nt=0;nt<8;nt++){
                bf0[nt][0] = Bb[nt*8*BS1_STRIDE];
                bf0[nt][1] = Bb[nt*8*BS1_STRIDE + 4];
            }
        }
    }

    const int nk = Ki >> 4;
    int buf = 0;
    for (int t = 0; t < nk; ++t){
        // load frag group1 (ks=8) from current buffer
        {
            const unsigned* Ab = As + buf*AS_HALF + a_frag_off + 8;
            #pragma unroll
            for (int mt=0;mt<4;mt++){
                const unsigned* p = Ab + (mt*16)*AS_STRIDE;
                af1[mt][0] = p[0];
                af1[mt][1] = p[8*AS_STRIDE];
                af1[mt][2] = p[4];
                af1[mt][3] = p[8*AS_STRIDE+4];
            }
            if (TB==0){
                const unsigned* Bb = Bs + buf*BS0_HALF + b0_frag_off + 8*BS0_STRIDE;
                #pragma unroll
                for (int nt=0;nt<8;nt++){
                    bf1[nt][0] = Bb[nt*8];
                    bf1[nt][1] = Bb[4*BS0_STRIDE + nt*8];
                }
            } else {
                const unsigned* Bb = Bs + buf*BS1_HALF + b1_frag_off + 8;
                #pragma unroll
                for (int nt=0;nt<8;nt++){
                    bf1[nt][0] = Bb[nt*8*BS1_STRIDE];
                    bf1[nt][1] = Bb[nt*8*BS1_STRIDE + 4];
                }
            }
        }
        // prefetch next global tile
        if (t+1 < nk){
            int kt = (t+1)<<4;
            #pragma unroll
            for (int i=0;i<2;i++)
                pA[i] = *(const float4*)(A + (long long)(row0 + a_r + i*64)*lda + kt + a_kc);
            if (TB==0){
                #pragma unroll
                for (int i=0;i<4;i++)
                    pB[i] = *(const float4*)(Bm + (long long)(kt + b0_k + i*4)*ldb + col0 + b0_n);
            } else {
                #pragma unroll
                for (int i=0;i<4;i++)
                    pB[i] = *(const float4*)(Bm + (long long)(col0 + b1_n + i*64)*ldb + kt + b1_kc);
            }
        }
        // MMA group 0
        #pragma unroll
        for (int mt=0;mt<4;mt++)
            #pragma unroll
            for (int nt=0;nt<8;nt++)
                mma_tf32(acc[mt][nt], af0[mt][0],af0[mt][1],af0[mt][2],af0[mt][3],
                         bf0[nt][0],bf0[nt][1]);
        // MMA group 1
        #pragma unroll
        for (int mt=0;mt<4;mt++)
            #pragma unroll
            for (int nt=0;nt<8;nt++)
                mma_tf32(acc[mt][nt], af1[mt][0],af1[mt][1],af1[mt][2],af1[mt][3],
                         bf1[nt][0],bf1[nt][1]);
        // store prefetched tile into other buffer
        if (t+1 < nk){
            int ob = buf^1;
            #pragma unroll
            for (int i=0;i<2;i++)
                *(uint4*)&As[ob*AS_HALF + (a_r + i*64)*AS_STRIDE + a_kc] = cvt4(pA[i]);
            if (TB==0){
                #pragma unroll
                for (int i=0;i<4;i++)
                    *(uint4*)&Bs[ob*BS0_HALF + (b0_k + i*4)*BS0_STRIDE + b0_n] = cvt4(pB[i]);
            } else {
                #pragma unroll
                for (int i=0;i<4;i++)
                    *(uint4*)&Bs[ob*BS1_HALF + (b1_n + i*64)*BS1_STRIDE + b1_kc] = cvt4(pB[i]);
            }
        }
        __syncthreads();
        buf ^= 1;
        // load frag group0 of new buffer
        if (t+1 < nk){
            const unsigned* Ab = As + buf*AS_HALF + a_frag_off;
            #pragma unroll
            for (int mt=0;mt<4;mt++){
                const unsigned* p = Ab + (mt*16)*AS_STRIDE;
                af0[mt][0] = p[0];
                af0[mt][1] = p[8*AS_STRIDE];
                af0[mt][2] = p[4];
                af0[mt][3] = p[8*AS_STRIDE+4];
            }
            if (TB==0){
                const unsigned* Bb = Bs + buf*BS0_HALF + b0_frag_off;
                #pragma unroll
                for (int nt=0;nt<8;nt++){
                    bf0[nt][0] = Bb[nt*8];
                    bf0[nt][1] = Bb[4*BS0_STRIDE + nt*8];
                }
            } else {
                const unsigned* Bb = Bs + buf*BS1_HALF + b1_frag_off;
                #pragma unroll
                for (int nt=0;nt<8;nt++){
                    bf0[nt][0] = Bb[nt*8*BS1_STRIDE];
                    bf0[nt][1] = Bb[nt*8*BS1_STRIDE + 4];
                }
            }
        }
    }

    // epilogue
    #pragma unroll
    for (int mt=0;mt<4;mt++){
        int r = row0 + wm*64 + mt*16 + g;
        #pragma unroll
        for (int nt=0;nt<8;nt++){
            int cc = col0 + wn*64 + nt*8 + 2*qc;
            store2<EPI>(C, C2, ldc, r,   cc, acc[mt][nt][0], acc[mt][nt][1], alpha, bias);
            store2<EPI>(C, C2, ldc, r+8, cc, acc[mt][nt][2], acc[mt][nt][3], alpha, bias);
        }
    }
}

// ---------------- generic 64x64 tiled SIMT GEMM (small-N fallback) --------
template<int TB, int EPI>
__global__ void __launch_bounds__(256) gemm_kernel(
    int Ki,
    const float* __restrict__ A, int lda, long long sA,
    const float* __restrict__ Bm, int ldb, long long sB,
    float* __restrict__ C, int ldc, long long sC,
    float alpha, const float* __restrict__ bias)
{
    const int bz = blockIdx.z;
    A  += (long long)bz * sA;
    Bm += (long long)bz * sB;
    C  += (long long)bz * sC;
    const int row0 = blockIdx.y * 64;
    const int col0 = blockIdx.x * 64;
    __shared__ float As[16][68];
    __shared__ float Bs[16][68];
    const int tid = threadIdx.x;
    const int ty = tid >> 4, tx = tid & 15;
    const int ar = tid >> 2, akq = (tid & 3) << 2;

    float acc[4][4];
    #pragma unroll
    for (int i=0;i<4;i++)
        #pragma unroll
        for (int j=0;j<4;j++) acc[i][j]=0.f;

    for (int k0 = 0; k0 < Ki; k0 += 16) {
        float4 av = *(const float4*)(A + (long long)(row0+ar)*lda + k0 + akq);
        As[akq+0][ar]=av.x; As[akq+1][ar]=av.y; As[akq+2][ar]=av.z; As[akq+3][ar]=av.w;
        if (TB==0) {
            int bkk = tid >> 4, bc = (tid & 15) << 2;
            float4 bv = *(const float4*)(Bm + (long long)(k0+bkk)*ldb + col0 + bc);
            Bs[bkk][bc+0]=bv.x; Bs[bkk][bc+1]=bv.y; Bs[bkk][bc+2]=bv.z; Bs[bkk][bc+3]=bv.w;
        } else {
            int bc = tid >> 2, bkq = (tid & 3) << 2;
            float4 bv = *(const float4*)(Bm + (long long)(col0+bc)*ldb + k0 + bkq);
            Bs[bkq+0][bc]=bv.x; Bs[bkq+1][bc]=bv.y; Bs[bkq+2][bc]=bv.z; Bs[bkq+3][bc]=bv.w;
        }
        __syncthreads();
        #pragma unroll
        for (int kk=0;kk<16;kk++){
            float a[4], b[4];
            #pragma unroll
            for (int i=0;i<4;i++) a[i]=As[kk][ty+16*i];
            #pragma unroll
            for (int j=0;j<4;j++) b[j]=Bs[kk][tx+16*j];
            #pragma unroll
            for (int i=0;i<4;i++)
                #pragma unroll
                for (int j=0;j<4;j++)
                    acc[i][j] = fmaf(a[i], b[j], acc[i][j]);
        }
        __syncthreads();
    }

    #pragma unroll
    for (int i=0;i<4;i++){
        int r = row0 + ty + 16*i;
        #pragma unroll
        for (int j=0;j<4;j++){
            int c = col0 + tx + 16*j;
            float val = alpha * acc[i][j];
            if (EPI==0) {
                C[(long long)r*ldc + c] = val;
            } else if (EPI==2) {
                float xg = val + bias[c];
                C[(long long)r*ldc + c] = 0.5f*xg*(1.f+erff(xg*0.70710678118654752f));
            } else if (EPI==3) {
                C[(long long)r*ldc + c] += val + bias[c];
            } else if (EPI==4) {
                int bb = r / NPAD, nl = r % NPAD;
                if (nl >= PADL)
                    C[((long long)bb*LSEQ + (nl-PADL))*ldc + c] += val + bias[c];
            }
        }
    }
}

// ---------------- elementwise / small kernels ----------------
__global__ void embed_kernel(const int* __restrict__ x,
                             const float* __restrict__ emb,
                             const float* __restrict__ pos){
    long long idx = (long long)blockIdx.x*blockDim.x + threadIdx.x;
    if (idx >= (long long)BATCH*LSEQ*DMODEL) return;
    int d = (int)(idx % DMODEL);
    long long bl = idx / DMODEL;
    int l = (int)(bl % LSEQ);
    int tok = x[bl];
    g_h[idx] = emb[(long long)tok*DMODEL + d] + pos[(long long)l*DMODEL + d];
}

__global__ void zero_pad_kernel(){
    int idx = blockIdx.x*blockDim.x + threadIdx.x;
    if (idx >= BATCH*PADL*DMODEL) return;
    int d  = idx % DMODEL;
    int bp = idx / DMODEL;
    int b  = bp / PADL, p = bp % PADL;
    g_x[((long long)b*NPAD + p)*DMODEL + d] = 0.f;
}

__global__ void ln_kernel(const float* __restrict__ in, float* __restrict__ out,
                          const float* __restrict__ gm, const float* __restrict__ bt,
                          int padmode){
    __shared__ float sh[8];
    int r = blockIdx.x;
    int t = threadIdx.x;
    const float* p = in + (long long)r*DMODEL;
    float a  = p[t];
    float b2 = p[t+256];
    float s  = blockSumN(a+b2, sh, 8);
    float mu = s * (1.f/512.f);
    float da = a - mu, db = b2 - mu;
    float v  = blockSumN(da*da + db*db, sh, 8) * (1.f/512.f);
    float rstd = rsqrtf(v + 1e-5f);
    long long orow = padmode ? ((long long)(r/LSEQ)*NPAD + PADL + (r%LSEQ)) : (long long)r;
    float* q = out + orow*DMODEL;
    q[t]     = da*rstd*gm[t]     + bt[t];
    q[t+256] = db*rstd*gm[t+256] + bt[t+256];
}

__global__ void qkv_split_kernel(){
    long long idx = (long long)blockIdx.x*blockDim.x + threadIdx.x;
    if (idx >= (long long)BH*NPAD*DHD) return;
    int d = (int)(idx & 63);
    long long r = idx >> 6;
    int n  = (int)(r % NPAD);
    int bh = (int)(r / NPAD);
    int h  = bh % NH, b = bh / NH;
    long long base = ((long long)b*NPAD + n)*(3*DMODEL) + h*DHD + d;
    g_q[idx] = g_qkv[base] * QSCALE;
    g_k[idx] = g_qkv[base + DMODEL];
    g_v[idx] = g_qkv[base + 2*DMODEL];
}

__global__ void landmark_kernel(){
    long long idx = (long long)blockIdx.x*blockDim.x + threadIdx.x;
    if (idx >= (long long)BH*ML*DHD) return;
    int d = (int)(idx & 63);
    long long r = idx >> 6;
    int m  = (int)(r % ML);
    int bh = (int)(r / ML);
    long long base = ((long long)bh*NPAD + (long long)m*LMR)*DHD + d;
    float sq = 0.f, sk = 0.f;
    #pragma unroll
    for (int j=0;j<LMR;j++){ sq += g_q[base + (long long)j*DHD]; sk += g_k[base + (long long)j*DHD]; }
    g_ql[idx] = sq * 0.25f;
    g_kl[idx] = sk * 0.25f;
}

__global__ void softmax_kernel(float* __restrict__ X, int cols){
    __shared__ float sh[4];
    long long row = blockIdx.x;
    float* p = X + row*(long long)cols;
    int t = threadIdx.x;
    int cnt = cols >> 7;
    float v[8];
    float mx = -3.4e38f;
    #pragma unroll
    for (int i=0;i<8;i++) if (i<cnt){ v[i]=p[t + (i<<7)]; mx = fmaxf(mx, v[i]); }
    mx = blockMaxN(mx, sh, 4);
    float s = 0.f;
    #pragma unroll
    for (int i=0;i<8;i++) if (i<cnt){ v[i]=expf(v[i]-mx); s += v[i]; }
    s = blockSumN(s, sh, 4);
    float inv = 1.f/s;
    #pragma unroll
    for (int i=0;i<8;i++) if (i<cnt) p[t + (i<<7)] = v[i]*inv;
}

__global__ void red_init_kernel(){ g_red[0]=0; g_red[1]=0; }

__global__ void colsum_kernel(){
    int idx = blockIdx.x*blockDim.x + threadIdx.x;
    if (idx >= BH*ML) return;
    int c  = idx % ML;
    int bz = idx / ML;
    const float* p = g_a2 + (long long)bz*ML*ML + c;
    float s = 0.f;
    for (int r2=0;r2<ML;r2++) s += fabsf(p[(long long)r2*ML]);
    atomicMax(&g_red[0], __float_as_int(s));
}
__global__ void rowsum_kernel(){
    int idx = blockIdx.x*blockDim.x + threadIdx.x;
    if (idx >= BH*ML) return;
    int r2 = idx % ML;
    int bz = idx / ML;
    const float* p = g_a2 + (long long)bz*ML*ML + (long long)r2*ML;
    float s = 0.f;
    for (int c=0;c<ML;c++) s += fabsf(p[c]);
    atomicMax(&g_red[1], __float_as_int(s));
}
__global__ void zinit_kernel(){
    long long idx = (long long)blockIdx.x*blockDim.x + threadIdx.x;
    if (idx >= (long long)BH*ML*ML) return;
    int j = (int)(idx % ML);
    long long r = idx / ML;
    int i  = (int)(r % ML);
    int bz = (int)(r / ML);
    float c = __int_as_float(g_red[0]) * __int_as_float(g_red[1]);
    g_zb[idx] = g_a2[((long long)bz*ML + j)*ML + i] / c;
}

__global__ void combine_kernel(const float* __restrict__ cw){
    long long idx = (long long)blockIdx.x*blockDim.x + threadIdx.x;
    if (idx >= (long long)BH*NPAD*DHD) return;
    int d = (int)(idx & 63);
    long long r = idx >> 6;
    int n  = (int)(r % NPAD);
    int bh = (int)(r / NPAD);
    int h  = bh % NH, b = bh / NH;
    float s = g_ao[idx];
    const float* w  = cw + h*KC;
    const float* vp = g_v + ((long long)bh*NPAD)*DHD + d;
    int k0 = (16-n > 0) ? (16-n) : 0;
    int k1 = (NPAD+16-n < KC) ? (NPAD+16-n) : KC;
    for (int kk=k0; kk<k1; kk++)
        s = fmaf(vp[(long long)(n+kk-16)*DHD], w[kk], s);
    g_y[((long long)b*NPAD + n)*DMODEL + h*DHD + d] = s;
}

__global__ void final_kernel(const float* __restrict__ fw,
                             const float* __restrict__ fb,
                             float* __restrict__ out){
    __shared__ float sh[8];
    int b = blockIdx.x;
    int t = threadIdx.x;
    const float* hp = g_h + (long long)b*LSEQ*DMODEL;
    float s = 0.f;
    for (long long i=t; i<(long long)LSEQ*DMODEL; i+=256)
        s = fmaf(hp[i], fw[i], s);
    s = blockSumN(s, sh, 8);
    if (t==0) out[b] = s + fb[0];
}

// ---------------- host-side GEMM dispatch ----------------
static void run_gemm(int tb, int epi, int Mi, int Ni, int Ki,
                     const float* A, int lda, long long sA,
                     const float* Bm, int ldb, long long sB,
                     float* C, int ldc, long long sC,
                     int batch, float alpha, const float* bias,
                     float* C2 = nullptr)
{
    if ((Mi % 128) == 0 && (Ni % 256) == 0 && (Ki % 16) == 0) {
        dim3 g(Ni/256, Mi/128, batch), t(256);
        size_t sh = SMEM_TC_BYTES;
        if (tb == 0) {
            switch (epi) {
                case 0: gemm_tc_kernel<0,0><<<g,t,sh>>>(Ki,A,lda,sA,Bm,ldb,sB,C,ldc,sC,alpha,bias,C2); break;
                case 2: gemm_tc_kernel<0,2><<<g,t,sh>>>(Ki,A,lda,sA,Bm,ldb,sB,C,ldc,sC,alpha,bias,C2); break;
                case 3: gemm_tc_kernel<0,3><<<g,t,sh>>>(Ki,A,lda,sA,Bm,ldb,sB,C,ldc,sC,alpha,bias,C2); break;
                case 4: gemm_tc_kernel<0,4><<<g,t,sh>>>(Ki,A,lda,sA,Bm,ldb,sB,C,ldc,sC,alpha,bias,C2); break;
                case 5: gemm_tc_kernel<0,5><<<g,t,sh>>>(Ki,A,lda,sA,Bm,ldb,sB,C,ldc,sC,alpha,bias,C2); break;
                case 6: gemm_tc_kernel<0,6><<<g,t,sh>>>(Ki,A,lda,sA,Bm,ldb,sB,C,ldc,sC,alpha,bias,C2); break;
            }
        } else {
            gemm_tc_kernel<1,0><<<g,t,sh>>>(Ki,A,lda,sA,Bm,ldb,sB,C,ldc,sC,alpha,bias,C2);
        }
        return;
    }
    dim3 g(Ni/64, Mi/64, batch), t(256);
    if (tb==0){
        if      (epi==0) gemm_kernel<0,0><<<g,t>>>(Ki,A,lda,sA,Bm,ldb,sB,C,ldc,sC,alpha,bias);
        else if (epi==2) gemm_kernel<0,2><<<g,t>>>(Ki,A,lda,sA,Bm,ldb,sB,C,ldc,sC,alpha,bias);
        else if (epi==3) gemm_kernel<0,3><<<g,t>>>(Ki,A,lda,sA,Bm,ldb,sB,C,ldc,sC,alpha,bias);
        else             gemm_kernel<0,4><<<g,t>>>(Ki,A,lda,sA,Bm,ldb,sB,C,ldc,sC,alpha,bias);
    } else {
        gemm_kernel<1,0><<<g,t>>>(Ki,A,lda,sA,Bm,ldb,sB,C,ldc,sC,alpha,bias);
    }
}

static void setup_tc_attrs(){
    cudaFuncSetAttribute(gemm_tc_kernel<0,0>, cudaFuncAttributeMaxDynamicSharedMemorySize, SMEM_TC_BYTES);
    cudaFuncSetAttribute(gemm_tc_kernel<0,2>, cudaFuncAttributeMaxDynamicSharedMemorySize, SMEM_TC_BYTES);
    cudaFuncSetAttribute(gemm_tc_kernel<0,3>, cudaFuncAttributeMaxDynamicSharedMemorySize, SMEM_TC_BYTES);
    cudaFuncSetAttribute(gemm_tc_kernel<0,4>, cudaFuncAttributeMaxDynamicSharedMemorySize, SMEM_TC_BYTES);
    cudaFuncSetAttribute(gemm_tc_kernel<0,5>, cudaFuncAttributeMaxDynamicSharedMemorySize, SMEM_TC_BYTES);
    cudaFuncSetAttribute(gemm_tc_kernel<0,6>, cudaFuncAttributeMaxDynamicSharedMemorySize, SMEM_TC_BYTES);
    cudaFuncSetAttribute(gemm_tc_kernel<1,0>, cudaFuncAttributeMaxDynamicSharedMemorySize, SMEM_TC_BYTES);
}

extern "C" void kernel_launch(void* const* d_in, const int* in_sizes, int n_in,
                              void* d_out, int out_size)
{
    (void)in_sizes; (void)n_in; (void)out_size;
    const int*   x       = (const int*)  d_in[0];
    const float* enc_emb = (const float*)d_in[1];
    const float* pos_emb = (const float*)d_in[2];
    const float* ln1_s   = (const float*)d_in[3];
    const float* ln1_b   = (const float*)d_in[4];
    const float* qkv_w   = (const float*)d_in[5];
    const float* aout_w  = (const float*)d_in[6];
    const float* aout_b  = (const float*)d_in[7];
    const float* conv_k  = (const float*)d_in[8];
    const float* ln2_s   = (const float*)d_in[9];
    const float* ln2_b   = (const float*)d_in[10];
    const float* ff_w1   = (const float*)d_in[11];
    const float* ff_b1   = (const float*)d_in[12];
    const float* ff_w2   = (const float*)d_in[13];
    const float* ff_b2   = (const float*)d_in[14];
    const float* fin_w   = (const float*)d_in[15];
    const float* fin_b   = (const float*)d_in[16];
    float* out = (float*)d_out;

    setup_tc_attrs();

    float *p_h,*p_x,*p_qkv,*p_q,*p_k,*p_v,*p_ql,*p_kl,*p_a1,*p_a3,*p_a2;
    float *p_z,*p_z2,*p_p,*p_t,*p_t2,*p_kv,*p_a1z,*p_ao,*p_y,*p_x2,*p_ff;
    cudaGetSymbolAddress((void**)&p_h,  g_h);
    cudaGetSymbolAddress((void**)&p_x,  g_x);
    cudaGetSymbolAddress((void**)&p_qkv,g_qkv);
    cudaGetSymbolAddress((void**)&p_q,  g_q);
    cudaGetSymbolAddress((void**)&p_k,  g_k);
    cudaGetSymbolAddress((void**)&p_v,  g_v);
    cudaGetSymbolAddress((void**)&p_ql, g_ql);
    cudaGetSymbolAddress((void**)&p_kl, g_kl);
    cudaGetSymbolAddress((void**)&p_a1, g_a1);
    cudaGetSymbolAddress((void**)&p_a3, g_a3);
    cudaGetSymbolAddress((void**)&p_a2, g_a2);
    cudaGetSymbolAddress((void**)&p_z,  g_zb);
    cudaGetSymbolAddress((void**)&p_z2, g_zb2);
    cudaGetSymbolAddress((void**)&p_p,  g_pb);
    cudaGetSymbolAddress((void**)&p_t,  g_tb);
    cudaGetSymbolAddress((void**)&p_t2, g_tb2);
    cudaGetSymbolAddress((void**)&p_kv, g_kvb);
    cudaGetSymbolAddress((void**)&p_a1z,g_a1z);
    cudaGetSymbolAddress((void**)&p_ao, g_ao);
    cudaGetSymbolAddress((void**)&p_y,  g_y);
    cudaGetSymbolAddress((void**)&p_x2, g_x2);
    cudaGetSymbolAddress((void**)&p_ff, g_ff);

    const long long MM  = (long long)ML*ML;
    const long long NM  = (long long)NPAD*ML;
    const long long ND  = (long long)NPAD*DHD;
    const long long MD  = (long long)ML*DHD;

    {
        long long tot = (long long)BATCH*LSEQ*DMODEL;
        embed_kernel<<<(unsigned)((tot+255)/256),256>>>(x, enc_emb, pos_emb);
        int tot2 = BATCH*PADL*DMODEL;
        zero_pad_kernel<<<(tot2+255)/256,256>>>();
    }

    for (int lay=0; lay<DEPTH; lay++){
        ln_kernel<<<BATCH*LSEQ,256>>>(p_h, p_x, ln1_s+(long long)lay*DMODEL, ln1_b+(long long)lay*DMODEL, 1);
        // QKV [tensor]
        run_gemm(0,0, BATCH*NPAD, 3*DMODEL, DMODEL,
                 p_x, DMODEL, 0,
                 qkv_w + (long long)lay*DMODEL*3*DMODEL, 3*DMODEL, 0,
                 p_qkv, 3*DMODEL, 0, 1, 1.f, nullptr);
        {
            long long tot = (long long)BH*NPAD*DHD;
            qkv_split_kernel<<<(unsigned)((tot+255)/256),256>>>();
            long long tot2 = (long long)BH*ML*DHD;
            landmark_kernel<<<(unsigned)((tot2+255)/256),256>>>();
        }
        // attn1 = softmax(q @ kl^T)  [tensor TB=1]
        run_gemm(1,0, NPAD, ML, DHD, p_q, DHD, ND, p_kl, DHD, MD, p_a1, ML, NM, BH, 1.f, nullptr);
        softmax_kernel<<<BH*NPAD,128>>>(p_a1, ML);
        // attn2 = softmax(ql @ kl^T)  [tensor TB=1]
        run_gemm(1,0, ML, ML, DHD, p_ql, DHD, MD, p_kl, DHD, MD, p_a2, ML, MM, BH, 1.f, nullptr);
        softmax_kernel<<<BH*ML,128>>>(p_a2, ML);
        // attn3 = softmax(ql @ k^T)  [tensor TB=1]
        run_gemm(1,0, ML, NPAD, DHD, p_ql, DHD, MD, p_k, DHD, ND, p_a3, NPAD, (long long)ML*NPAD, BH, 1.f, nullptr);
        softmax_kernel<<<BH*ML,128>>>(p_a3, NPAD);

        // ---- pinv (tensor, fused aI-X epilogues) ----
        red_init_kernel<<<1,1>>>();
        colsum_kernel<<<(BH*ML+255)/256,256>>>();
        rowsum_kernel<<<(BH*ML+255)/256,256>>>();
        {
            long long tot = (long long)BH*ML*ML;
            unsigned g = (unsigned)((tot+255)/256);
            zinit_kernel<<<g,256>>>();
        }
        float* zc = p_z; float* zn = p_z2;
        for (int it=0; it<6; it++){
            run_gemm(0,6, ML, ML, ML, p_a2, ML, MM, zc, ML, MM, p_p, ML, MM, BH, 7.f, nullptr, p_t);
            run_gemm(0,5, ML, ML, ML, p_p, ML, MM, p_t, ML, MM, p_t2, ML, MM, BH, 15.f, nullptr);
            run_gemm(0,5, ML, ML, ML, p_p, ML, MM, p_t2, ML, MM, p_t, ML, MM, BH, 13.f, nullptr);
            run_gemm(0,0, ML, ML, ML, zc, ML, MM, p_t, ML, MM, zn, ML, MM, BH, 0.25f, nullptr);
            float* tmp = zc; zc = zn; zn = tmp;
        }

        // kv = attn3 @ v  [SIMT N=64]
        run_gemm(0,0, ML, DHD, NPAD, p_a3, NPAD, (long long)ML*NPAD, p_v, DHD, ND, p_kv, DHD, MD, BH, 1.f, nullptr);
        // a1z = attn1 @ Z  [tensor]
        run_gemm(0,0, NPAD, ML, ML, p_a1, ML, NM, zc, ML, MM, p_a1z, ML, NM, BH, 1.f, nullptr);
        // ao = a1z @ kv  [SIMT N=64]
        run_gemm(0,0, NPAD, DHD, ML, p_a1z, ML, NM, p_kv, DHD, MD, p_ao, DHD, ND, BH, 1.f, nullptr);
        {
            long long tot = (long long)BH*NPAD*DHD;
            combine_kernel<<<(unsigned)((tot+255)/256),256>>>(conv_k + (long long)lay*NH*KC);
        }
        // out projection + residual [tensor]
        run_gemm(0,4, BATCH*NPAD, DMODEL, DMODEL,
                 p_y, DMODEL, 0,
                 aout_w + (long long)lay*DMODEL*DMODEL, DMODEL, 0,
                 p_h, DMODEL, 0, 1, 1.f, aout_b + (long long)lay*DMODEL);

        // ---- FFN ----
        ln_kernel<<<BATCH*LSEQ,256>>>(p_h, p_x2, ln2_s+(long long)lay*DMODEL, ln2_b+(long long)lay*DMODEL, 0);
        run_gemm(0,2, BATCH*LSEQ, FFD, DMODEL,
                 p_x2, DMODEL, 0,
                 ff_w1 + (long long)lay*DMODEL*FFD, FFD, 0,
                 p_ff, FFD, 0, 1, 1.f, ff_b1 + (long long)lay*FFD);
        run_gemm(0,3, BATCH*LSEQ, DMODEL, FFD,
                 p_ff, FFD, 0,
                 ff_w2 + (long long)lay*FFD*DMODEL, DMODEL, 0,
                 p_h, DMODEL, 0, 1, 1.f, ff_b2 + (long long)lay*DMODEL);
    }

    final_kernel<<<BATCH,256>>>(fin_w, fin_b, out);
}

// round 5
// speedup vs baseline: 3.1698x; 1.0955x over previous
#include <cuda_runtime.h>
#include <math.h>
#include <stdint.h>

// ---------------- model constants ----------------
#define BATCH 16
#define LSEQ  1000
#define DMODEL 512
#define NH    8
#define DHD   64
#define NPAD  1024
#define PADL  24
#define ML    256
#define LMR   4
#define FFD   2048
#define DEPTH 6
#define KC    33
#define QSCALE 0.125f
#define BH (BATCH*NH)

// ---------------- scratch ----------------
__device__ float g_h   [BATCH*LSEQ*DMODEL];
__device__ float g_x   [BATCH*NPAD*DMODEL];
__device__ float g_qkv [BATCH*NPAD*3*DMODEL];
__device__ float g_q   [BH*NPAD*DHD];
__device__ float g_k   [BH*NPAD*DHD];
__device__ float g_v   [BH*NPAD*DHD];
__device__ float g_ql  [BH*ML*DHD];
__device__ float g_kl  [BH*ML*DHD];
__device__ float g_a1  [BH*NPAD*ML];
__device__ float g_a3  [BH*ML*NPAD];
__device__ float g_a2  [BH*ML*ML];
__device__ float g_zb  [BH*ML*ML];
__device__ float g_zb2 [BH*ML*ML];
__device__ float g_pb  [BH*ML*ML];
__device__ float g_tb  [BH*ML*ML];
__device__ float g_tb2 [BH*ML*ML];
__device__ float g_kvb [BH*ML*DHD];
__device__ float g_a1z [BH*NPAD*ML];
__device__ float g_ao  [BH*NPAD*DHD];
__device__ float g_y   [BATCH*NPAD*DMODEL];
__device__ float g_x2  [BATCH*LSEQ*DMODEL];
__device__ float g_ff  [BATCH*LSEQ*FFD];
__device__ int   g_red [2];

// ---------------- reductions ----------------
__device__ __forceinline__ float warpSum(float v){
    #pragma unroll
    for (int o=16;o;o>>=1) v += __shfl_xor_sync(0xffffffffu, v, o);
    return v;
}
__device__ __forceinline__ float warpMax(float v){
    #pragma unroll
    for (int o=16;o;o>>=1) v = fmaxf(v, __shfl_xor_sync(0xffffffffu, v, o));
    return v;
}
__device__ __forceinline__ float blockSumN(float v, float* sh, int nw){
    int w = threadIdx.x>>5, l = threadIdx.x&31;
    v = warpSum(v);
    if (l==0) sh[w] = v;
    __syncthreads();
    if (w==0){
        float x = (l < nw) ? sh[l] : 0.f;
        x = warpSum(x);
        if (l==0) sh[0] = x;
    }
    __syncthreads();
    float r = sh[0];
    __syncthreads();
    return r;
}
__device__ __forceinline__ float blockMaxN(float v, float* sh, int nw){
    int w = threadIdx.x>>5, l = threadIdx.x&31;
    v = warpMax(v);
    if (l==0) sh[w] = v;
    __syncthreads();
    if (w==0){
        float x = (l < nw) ? sh[l] : -3.4e38f;
        x = warpMax(x);
        if (l==0) sh[0] = x;
    }
    __syncthreads();
    float r = sh[0];
    __syncthreads();
    return r;
}

// ---------------- mma / cp.async helpers ----------------
__device__ __forceinline__ void mma_tf32(float c[4],
    unsigned a0, unsigned a1, unsigned a2, unsigned a3,
    unsigned b0, unsigned b1)
{
    asm volatile(
        "mma.sync.aligned.m16n8k8.row.col.f32.tf32.tf32.f32 "
        "{%0,%1,%2,%3}, {%4,%5,%6,%7}, {%8,%9}, {%0,%1,%2,%3};"
        : "+f"(c[0]), "+f"(c[1]), "+f"(c[2]), "+f"(c[3])
        : "r"(a0), "r"(a1), "r"(a2), "r"(a3), "r"(b0), "r"(b1));
}
__device__ __forceinline__ void cp16(unsigned saddr, const void* gptr){
    asm volatile("cp.async.cg.shared.global [%0], [%1], 16;\n"
                 :: "r"(saddr), "l"(gptr));
}
__device__ __forceinline__ void cp_commit(){
    asm volatile("cp.async.commit_group;\n");
}
template<int N>
__device__ __forceinline__ void cp_wait(){
    asm volatile("cp.async.wait_group %0;\n" :: "n"(N));
}

// epilogue: writes 2 consecutive cols at (r, cc)
template<int EPI>
__device__ __forceinline__ void store2(
    float* __restrict__ C, float* __restrict__ C2, int ldc,
    int r, int cc, float v0, float v1,
    float alpha, const float* __restrict__ bias)
{
    if (EPI==0){
        float2 o = {alpha*v0, alpha*v1};
        *(float2*)&C[(long long)r*ldc + cc] = o;
    } else if (EPI==2){
        float x0 = v0 + bias[cc], x1 = v1 + bias[cc+1];
        float2 o;
        o.x = 0.5f*x0*(1.f+erff(x0*0.70710678118654752f));
        o.y = 0.5f*x1*(1.f+erff(x1*0.70710678118654752f));
        *(float2*)&C[(long long)r*ldc + cc] = o;
    } else if (EPI==3){
        float2 o = *(float2*)&C[(long long)r*ldc + cc];
        o.x += v0 + bias[cc];
        o.y += v1 + bias[cc+1];
        *(float2*)&C[(long long)r*ldc + cc] = o;
    } else if (EPI==4){
        int bb = r / NPAD, nl = r % NPAD;
        if (nl >= PADL){
            long long orow = (long long)bb*LSEQ + (nl - PADL);
            float2 o = *(float2*)&C[orow*ldc + cc];
            o.x += v0 + bias[cc];
            o.y += v1 + bias[cc+1];
            *(float2*)&C[orow*ldc + cc] = o;
        }
    } else if (EPI==5){
        float2 o = {(r==cc ? alpha : 0.f) - v0, (r==cc+1 ? alpha : 0.f) - v1};
        *(float2*)&C[(long long)r*ldc + cc] = o;
    } else if (EPI==6){
        float2 o = {v0, v1};
        *(float2*)&C[(long long)r*ldc + cc] = o;
        float2 o2 = {(r==cc ? alpha : 0.f) - v0, (r==cc+1 ? alpha : 0.f) - v1};
        *(float2*)&C2[(long long)r*ldc + cc] = o2;
    }
}

// ===== TF32 tensor GEMM v3: CTA 128x256, K-tile 16, 3-stage cp.async ======
// TB=0: B is KxN rm.  TB=1: B is NxK rm (C = A @ B^T).
// Requires M%128==0, N%256==0, K%16==0.
#define AS_STRIDE 20
#define AS_ST     (128*AS_STRIDE)      // words per A stage
#define BS0_STRIDE 264
#define BS1_STRIDE 20
#define BS_ST     (256*BS1_STRIDE)     // words per B stage (max: 5120 >= 16*264=4224)
#define NSTAGE 3
#define SMEM_TC_BYTES (NSTAGE*(AS_ST + BS_ST)*4)   // 92160

template<int TB, int EPI>
__global__ void __launch_bounds__(256,1) gemm_tc_kernel(
    int Ki,
    const float* __restrict__ A, int lda, long long sA,
    const float* __restrict__ Bm, int ldb, long long sB,
    float* __restrict__ C, int ldc, long long sC,
    float alpha, const float* __restrict__ bias, float* __restrict__ C2)
{
    extern __shared__ unsigned sm[];
    unsigned* As = sm;
    unsigned* Bs = sm + NSTAGE*AS_ST;
    const unsigned As_base = (unsigned)__cvta_generic_to_shared(As);
    const unsigned Bs_base = (unsigned)__cvta_generic_to_shared(Bs);

    const int bz = blockIdx.z;
    A  += (long long)bz*sA;
    Bm += (long long)bz*sB;
    C  += (long long)bz*sC;
    if (EPI==6) C2 += (long long)bz*sC;

    const int row0 = blockIdx.y*128;
    const int col0 = blockIdx.x*256;
    const int tid = threadIdx.x;
    const int warp = tid>>5, lane = tid&31;
    const int wm = warp & 1, wn = warp >> 1;   // 2x4 warp grid, warp tile 64x64
    const int g = lane>>2, qc = lane&3;

    // staging maps
    const int a_r  = tid>>2;
    const int a_kc = (tid&3)<<2;
    const int b0_k = tid>>6;
    const int b0_n = (tid&63)<<2;
    const int b1_n = tid>>2;
    const int b1_kc = (tid&3)<<2;

    // per-stage issue (copies one 16-wide K slice at k-offset kt into buffer st)
    auto issue = [&](int kt, int st){
        unsigned abase = As_base + (unsigned)(st*AS_ST)*4u;
        #pragma unroll
        for (int i=0;i<2;i++)
            cp16(abase + (unsigned)((a_r + i*64)*AS_STRIDE + a_kc)*4u,
                 A + (long long)(row0 + a_r + i*64)*lda + kt + a_kc);
        unsigned bbase = Bs_base + (unsigned)(st*BS_ST)*4u;
        if (TB==0){
            #pragma unroll
            for (int i=0;i<4;i++)
                cp16(bbase + (unsigned)((b0_k + i*4)*BS0_STRIDE + b0_n)*4u,
                     Bm + (long long)(kt + b0_k + i*4)*ldb + col0 + b0_n);
        } else {
            #pragma unroll
            for (int i=0;i<4;i++)
                cp16(bbase + (unsigned)((b1_n + i*64)*BS1_STRIDE + b1_kc)*4u,
                     Bm + (long long)(col0 + b1_n + i*64)*ldb + kt + b1_kc);
        }
    };

    float acc[4][8][4];
    #pragma unroll
    for (int mt=0;mt<4;mt++)
        #pragma unroll
        for (int nt=0;nt<8;nt++)
            #pragma unroll
            for (int i=0;i<4;i++) acc[mt][nt][i]=0.f;

    const int nk = Ki >> 4;
    // prologue: issue stages 0,1
    issue(0, 0);  cp_commit();
    issue(16, 1); cp_commit();

    // fragment bases (word offsets within a buffer)
    const int a_frag_off  = (wm*64 + g)*AS_STRIDE + qc;
    const int b0_frag_off = qc*BS0_STRIDE + wn*64 + g;
    const int b1_frag_off = (wn*64 + g)*BS1_STRIDE + qc;

    unsigned af0[4][4], bf0[8][2], af1[4][4], bf1[8][2];

    for (int t = 0; t < nk; ++t){
        cp_wait<1>();          // stage t complete
        __syncthreads();
        const int rb = t % NSTAGE;
        // frag group0 (ks=0..7)
        {
            const unsigned* Ab = As + rb*AS_ST + a_frag_off;
            #pragma unroll
            for (int mt=0;mt<4;mt++){
                const unsigned* p = Ab + (mt*16)*AS_STRIDE;
                af0[mt][0] = p[0];
                af0[mt][1] = p[8*AS_STRIDE];
                af0[mt][2] = p[4];
                af0[mt][3] = p[8*AS_STRIDE+4];
            }
            if (TB==0){
                const unsigned* Bb = Bs + rb*BS_ST + b0_frag_off;
                #pragma unroll
                for (int nt=0;nt<8;nt++){
                    bf0[nt][0] = Bb[nt*8];
                    bf0[nt][1] = Bb[4*BS0_STRIDE + nt*8];
                }
            } else {
                const unsigned* Bb = Bs + rb*BS_ST + b1_frag_off;
                #pragma unroll
                for (int nt=0;nt<8;nt++){
                    bf0[nt][0] = Bb[nt*8*BS1_STRIDE];
                    bf0[nt][1] = Bb[nt*8*BS1_STRIDE + 4];
                }
            }
        }
        // issue stage t+2
        if (t+2 < nk) issue((t+2)<<4, (t+2)%NSTAGE);
        cp_commit();
        // frag group1 (ks=8..15)
        {
            const unsigned* Ab = As + rb*AS_ST + a_frag_off + 8;
            #pragma unroll
            for (int mt=0;mt<4;mt++){
                const unsigned* p = Ab + (mt*16)*AS_STRIDE;
                af1[mt][0] = p[0];
                af1[mt][1] = p[8*AS_STRIDE];
                af1[mt][2] = p[4];
                af1[mt][3] = p[8*AS_STRIDE+4];
            }
            if (TB==0){
                const unsigned* Bb = Bs + rb*BS_ST + b0_frag_off + 8*BS0_STRIDE;
                #pragma unroll
                for (int nt=0;nt<8;nt++){
                    bf1[nt][0] = Bb[nt*8];
                    bf1[nt][1] = Bb[4*BS0_STRIDE + nt*8];
                }
            } else {
                const unsigned* Bb = Bs + rb*BS_ST + b1_frag_off + 8;
                #pragma unroll
                for (int nt=0;nt<8;nt++){
                    bf1[nt][0] = Bb[nt*8*BS1_STRIDE];
                    bf1[nt][1] = Bb[nt*8*BS1_STRIDE + 4];
                }
            }
        }
        // MMAs
        #pragma unroll
        for (int mt=0;mt<4;mt++)
            #pragma unroll
            for (int nt=0;nt<8;nt++)
                mma_tf32(acc[mt][nt], af0[mt][0],af0[mt][1],af0[mt][2],af0[mt][3],
                         bf0[nt][0],bf0[nt][1]);
        #pragma unroll
        for (int mt=0;mt<4;mt++)
            #pragma unroll
            for (int nt=0;nt<8;nt++)
                mma_tf32(acc[mt][nt], af1[mt][0],af1[mt][1],af1[mt][2],af1[mt][3],
                         bf1[nt][0],bf1[nt][1]);
    }

    // epilogue
    #pragma unroll
    for (int mt=0;mt<4;mt++){
        int r = row0 + wm*64 + mt*16 + g;
        #pragma unroll
        for (int nt=0;nt<8;nt++){
            int cc = col0 + wn*64 + nt*8 + 2*qc;
            store2<EPI>(C, C2, ldc, r,   cc, acc[mt][nt][0], acc[mt][nt][1], alpha, bias);
            store2<EPI>(C, C2, ldc, r+8, cc, acc[mt][nt][2], acc[mt][nt][3], alpha, bias);
        }
    }
}

// ---------------- generic 64x64 tiled SIMT GEMM (small-N fallback) --------
template<int TB, int EPI>
__global__ void __launch_bounds__(256) gemm_kernel(
    int Ki,
    const float* __restrict__ A, int lda, long long sA,
    const float* __restrict__ Bm, int ldb, long long sB,
    float* __restrict__ C, int ldc, long long sC,
    float alpha, const float* __restrict__ bias)
{
    const int bz = blockIdx.z;
    A  += (long long)bz * sA;
    Bm += (long long)bz * sB;
    C  += (long long)bz * sC;
    const int row0 = blockIdx.y * 64;
    const int col0 = blockIdx.x * 64;
    __shared__ float As[16][68];
    __shared__ float Bs[16][68];
    const int tid = threadIdx.x;
    const int ty = tid >> 4, tx = tid & 15;
    const int ar = tid >> 2, akq = (tid & 3) << 2;

    float acc[4][4];
    #pragma unroll
    for (int i=0;i<4;i++)
        #pragma unroll
        for (int j=0;j<4;j++) acc[i][j]=0.f;

    for (int k0 = 0; k0 < Ki; k0 += 16) {
        float4 av = *(const float4*)(A + (long long)(row0+ar)*lda + k0 + akq);
        As[akq+0][ar]=av.x; As[akq+1][ar]=av.y; As[akq+2][ar]=av.z; As[akq+3][ar]=av.w;
        if (TB==0) {
            int bkk = tid >> 4, bc = (tid & 15) << 2;
            float4 bv = *(const float4*)(Bm + (long long)(k0+bkk)*ldb + col0 + bc);
            Bs[bkk][bc+0]=bv.x; Bs[bkk][bc+1]=bv.y; Bs[bkk][bc+2]=bv.z; Bs[bkk][bc+3]=bv.w;
        } else {
            int bc = tid >> 2, bkq = (tid & 3) << 2;
            float4 bv = *(const float4*)(Bm + (long long)(col0+bc)*ldb + k0 + bkq);
            Bs[bkq+0][bc]=bv.x; Bs[bkq+1][bc]=bv.y; Bs[bkq+2][bc]=bv.z; Bs[bkq+3][bc]=bv.w;
        }
        __syncthreads();
        #pragma unroll
        for (int kk=0;kk<16;kk++){
            float a[4], b[4];
            #pragma unroll
            for (int i=0;i<4;i++) a[i]=As[kk][ty+16*i];
            #pragma unroll
            for (int j=0;j<4;j++) b[j]=Bs[kk][tx+16*j];
            #pragma unroll
            for (int i=0;i<4;i++)
                #pragma unroll
                for (int j=0;j<4;j++)
                    acc[i][j] = fmaf(a[i], b[j], acc[i][j]);
        }
        __syncthreads();
    }

    #pragma unroll
    for (int i=0;i<4;i++){
        int r = row0 + ty + 16*i;
        #pragma unroll
        for (int j=0;j<4;j++){
            int c = col0 + tx + 16*j;
            float val = alpha * acc[i][j];
            if (EPI==0) {
                C[(long long)r*ldc + c] = val;
            } else if (EPI==2) {
                float xg = val + bias[c];
                C[(long long)r*ldc + c] = 0.5f*xg*(1.f+erff(xg*0.70710678118654752f));
            } else if (EPI==3) {
                C[(long long)r*ldc + c] += val + bias[c];
            } else if (EPI==4) {
                int bb = r / NPAD, nl = r % NPAD;
                if (nl >= PADL)
                    C[((long long)bb*LSEQ + (nl-PADL))*ldc + c] += val + bias[c];
            }
        }
    }
}

// ---------------- elementwise / small kernels ----------------
__global__ void embed_kernel(const int* __restrict__ x,
                             const float* __restrict__ emb,
                             const float* __restrict__ pos){
    long long idx = (long long)blockIdx.x*blockDim.x + threadIdx.x;
    if (idx >= (long long)BATCH*LSEQ*DMODEL) return;
    int d = (int)(idx % DMODEL);
    long long bl = idx / DMODEL;
    int l = (int)(bl % LSEQ);
    int tok = x[bl];
    g_h[idx] = emb[(long long)tok*DMODEL + d] + pos[(long long)l*DMODEL + d];
}

__global__ void zero_pad_kernel(){
    int idx = blockIdx.x*blockDim.x + threadIdx.x;
    if (idx >= BATCH*PADL*DMODEL) return;
    int d  = idx % DMODEL;
    int bp = idx / DMODEL;
    int b  = bp / PADL, p = bp % PADL;
    g_x[((long long)b*NPAD + p)*DMODEL + d] = 0.f;
}

__global__ void ln_kernel(const float* __restrict__ in, float* __restrict__ out,
                          const float* __restrict__ gm, const float* __restrict__ bt,
                          int padmode){
    __shared__ float sh[8];
    int r = blockIdx.x;
    int t = threadIdx.x;
    const float* p = in + (long long)r*DMODEL;
    float a  = p[t];
    float b2 = p[t+256];
    float s  = blockSumN(a+b2, sh, 8);
    float mu = s * (1.f/512.f);
    float da = a - mu, db = b2 - mu;
    float v  = blockSumN(da*da + db*db, sh, 8) * (1.f/512.f);
    float rstd = rsqrtf(v + 1e-5f);
    long long orow = padmode ? ((long long)(r/LSEQ)*NPAD + PADL + (r%LSEQ)) : (long long)r;
    float* q = out + orow*DMODEL;
    q[t]     = da*rstd*gm[t]     + bt[t];
    q[t+256] = db*rstd*gm[t+256] + bt[t+256];
}

__global__ void qkv_split_kernel(){
    long long idx = (long long)blockIdx.x*blockDim.x + threadIdx.x;
    if (idx >= (long long)BH*NPAD*DHD) return;
    int d = (int)(idx & 63);
    long long r = idx >> 6;
    int n  = (int)(r % NPAD);
    int bh = (int)(r / NPAD);
    int h  = bh % NH, b = bh / NH;
    long long base = ((long long)b*NPAD + n)*(3*DMODEL) + h*DHD + d;
    g_q[idx] = g_qkv[base] * QSCALE;
    g_k[idx] = g_qkv[base + DMODEL];
    g_v[idx] = g_qkv[base + 2*DMODEL];
}

__global__ void landmark_kernel(){
    long long idx = (long long)blockIdx.x*blockDim.x + threadIdx.x;
    if (idx >= (long long)BH*ML*DHD) return;
    int d = (int)(idx & 63);
    long long r = idx >> 6;
    int m  = (int)(r % ML);
    int bh = (int)(r / ML);
    long long base = ((long long)bh*NPAD + (long long)m*LMR)*DHD + d;
    float sq = 0.f, sk = 0.f;
    #pragma unroll
    for (int j=0;j<LMR;j++){ sq += g_q[base + (long long)j*DHD]; sk += g_k[base + (long long)j*DHD]; }
    g_ql[idx] = sq * 0.25f;
    g_kl[idx] = sk * 0.25f;
}

__global__ void softmax_kernel(float* __restrict__ X, int cols){
    __shared__ float sh[4];
    long long row = blockIdx.x;
    float* p = X + row*(long long)cols;
    int t = threadIdx.x;
    int cnt = cols >> 7;
    float v[8];
    float mx = -3.4e38f;
    #pragma unroll
    for (int i=0;i<8;i++) if (i<cnt){ v[i]=p[t + (i<<7)]; mx = fmaxf(mx, v[i]); }
    mx = blockMaxN(mx, sh, 4);
    float s = 0.f;
    #pragma unroll
    for (int i=0;i<8;i++) if (i<cnt){ v[i]=expf(v[i]-mx); s += v[i]; }
    s = blockSumN(s, sh, 4);
    float inv = 1.f/s;
    #pragma unroll
    for (int i=0;i<8;i++) if (i<cnt) p[t + (i<<7)] = v[i]*inv;
}

__global__ void red_init_kernel(){ g_red[0]=0; g_red[1]=0; }

__global__ void colsum_kernel(){
    int idx = blockIdx.x*blockDim.x + threadIdx.x;
    if (idx >= BH*ML) return;
    int c  = idx % ML;
    int bz = idx / ML;
    const float* p = g_a2 + (long long)bz*ML*ML + c;
    float s = 0.f;
    for (int r2=0;r2<ML;r2++) s += fabsf(p[(long long)r2*ML]);
    atomicMax(&g_red[0], __float_as_int(s));
}
__global__ void rowsum_kernel(){
    int idx = blockIdx.x*blockDim.x + threadIdx.x;
    if (idx >= BH*ML) return;
    int r2 = idx % ML;
    int bz = idx / ML;
    const float* p = g_a2 + (long long)bz*ML*ML + (long long)r2*ML;
    float s = 0.f;
    for (int c=0;c<ML;c++) s += fabsf(p[c]);
    atomicMax(&g_red[1], __float_as_int(s));
}
__global__ void zinit_kernel(){
    long long idx = (long long)blockIdx.x*blockDim.x + threadIdx.x;
    if (idx >= (long long)BH*ML*ML) return;
    int j = (int)(idx % ML);
    long long r = idx / ML;
    int i  = (int)(r % ML);
    int bz = (int)(r / ML);
    float c = __int_as_float(g_red[0]) * __int_as_float(g_red[1]);
    g_zb[idx] = g_a2[((long long)bz*ML + j)*ML + i] / c;
}

__global__ void combine_kernel(const float* __restrict__ cw){
    long long idx = (long long)blockIdx.x*blockDim.x + threadIdx.x;
    if (idx >= (long long)BH*NPAD*DHD) return;
    int d = (int)(idx & 63);
    long long r = idx >> 6;
    int n  = (int)(r % NPAD);
    int bh = (int)(r / NPAD);
    int h  = bh % NH, b = bh / NH;
    float s = g_ao[idx];
    const float* w  = cw + h*KC;
    const float* vp = g_v + ((long long)bh*NPAD)*DHD + d;
    int k0 = (16-n > 0) ? (16-n) : 0;
    int k1 = (NPAD+16-n < KC) ? (NPAD+16-n) : KC;
    for (int kk=k0; kk<k1; kk++)
        s = fmaf(vp[(long long)(n+kk-16)*DHD], w[kk], s);
    g_y[((long long)b*NPAD + n)*DMODEL + h*DHD + d] = s;
}

__global__ void final_kernel(const float* __restrict__ fw,
                             const float* __restrict__ fb,
                             float* __restrict__ out){
    __shared__ float sh[8];
    int b = blockIdx.x;
    int t = threadIdx.x;
    const float* hp = g_h + (long long)b*LSEQ*DMODEL;
    float s = 0.f;
    for (long long i=t; i<(long long)LSEQ*DMODEL; i+=256)
        s = fmaf(hp[i], fw[i], s);
    s = blockSumN(s, sh, 8);
    if (t==0) out[b] = s + fb[0];
}

// ---------------- host-side GEMM dispatch ----------------
static void run_gemm(int tb, int epi, int Mi, int Ni, int Ki,
                     const float* A, int lda, long long sA,
                     const float* Bm, int ldb, long long sB,
                     float* C, int ldc, long long sC,
                     int batch, float alpha, const float* bias,
                     float* C2 = nullptr)
{
    if ((Mi % 128) == 0 && (Ni % 256) == 0 && (Ki % 16) == 0) {
        dim3 g(Ni/256, Mi/128, batch), t(256);
        size_t sh = SMEM_TC_BYTES;
        if (tb == 0) {
            switch (epi) {
                case 0: gemm_tc_kernel<0,0><<<g,t,sh>>>(Ki,A,lda,sA,Bm,ldb,sB,C,ldc,sC,alpha,bias,C2); break;
                case 2: gemm_tc_kernel<0,2><<<g,t,sh>>>(Ki,A,lda,sA,Bm,ldb,sB,C,ldc,sC,alpha,bias,C2); break;
                case 3: gemm_tc_kernel<0,3><<<g,t,sh>>>(Ki,A,lda,sA,Bm,ldb,sB,C,ldc,sC,alpha,bias,C2); break;
                case 4: gemm_tc_kernel<0,4><<<g,t,sh>>>(Ki,A,lda,sA,Bm,ldb,sB,C,ldc,sC,alpha,bias,C2); break;
                case 5: gemm_tc_kernel<0,5><<<g,t,sh>>>(Ki,A,lda,sA,Bm,ldb,sB,C,ldc,sC,alpha,bias,C2); break;
                case 6: gemm_tc_kernel<0,6><<<g,t,sh>>>(Ki,A,lda,sA,Bm,ldb,sB,C,ldc,sC,alpha,bias,C2); break;
            }
        } else {
            gemm_tc_kernel<1,0><<<g,t,sh>>>(Ki,A,lda,sA,Bm,ldb,sB,C,ldc,sC,alpha,bias,C2);
        }
        return;
    }
    dim3 g(Ni/64, Mi/64, batch), t(256);
    if (tb==0){
        if      (epi==0) gemm_kernel<0,0><<<g,t>>>(Ki,A,lda,sA,Bm,ldb,sB,C,ldc,sC,alpha,bias);
        else if (epi==2) gemm_kernel<0,2><<<g,t>>>(Ki,A,lda,sA,Bm,ldb,sB,C,ldc,sC,alpha,bias);
        else if (epi==3) gemm_kernel<0,3><<<g,t>>>(Ki,A,lda,sA,Bm,ldb,sB,C,ldc,sC,alpha,bias);
        else             gemm_kernel<0,4><<<g,t>>>(Ki,A,lda,sA,Bm,ldb,sB,C,ldc,sC,alpha,bias);
    } else {
        gemm_kernel<1,0><<<g,t>>>(Ki,A,lda,sA,Bm,ldb,sB,C,ldc,sC,alpha,bias);
    }
}

static void setup_tc_attrs(){
    cudaFuncSetAttribute(gemm_tc_kernel<0,0>, cudaFuncAttributeMaxDynamicSharedMemorySize, SMEM_TC_BYTES);
    cudaFuncSetAttribute(gemm_tc_kernel<0,2>, cudaFuncAttributeMaxDynamicSharedMemorySize, SMEM_TC_BYTES);
    cudaFuncSetAttribute(gemm_tc_kernel<0,3>, cudaFuncAttributeMaxDynamicSharedMemorySize, SMEM_TC_BYTES);
    cudaFuncSetAttribute(gemm_tc_kernel<0,4>, cudaFuncAttributeMaxDynamicSharedMemorySize, SMEM_TC_BYTES);
    cudaFuncSetAttribute(gemm_tc_kernel<0,5>, cudaFuncAttributeMaxDynamicSharedMemorySize, SMEM_TC_BYTES);
    cudaFuncSetAttribute(gemm_tc_kernel<0,6>, cudaFuncAttributeMaxDynamicSharedMemorySize, SMEM_TC_BYTES);
    cudaFuncSetAttribute(gemm_tc_kernel<1,0>, cudaFuncAttributeMaxDynamicSharedMemorySize, SMEM_TC_BYTES);
}

extern "C" void kernel_launch(void* const* d_in, const int* in_sizes, int n_in,
                              void* d_out, int out_size)
{
    (void)in_sizes; (void)n_in; (void)out_size;
    const int*   x       = (const int*)  d_in[0];
    const float* enc_emb = (const float*)d_in[1];
    const float* pos_emb = (const float*)d_in[2];
    const float* ln1_s   = (const float*)d_in[3];
    const float* ln1_b   = (const float*)d_in[4];
    const float* qkv_w   = (const float*)d_in[5];
    const float* aout_w  = (const float*)d_in[6];
    const float* aout_b  = (const float*)d_in[7];
    const float* conv_k  = (const float*)d_in[8];
    const float* ln2_s   = (const float*)d_in[9];
    const float* ln2_b   = (const float*)d_in[10];
    const float* ff_w1   = (const float*)d_in[11];
    const float* ff_b1   = (const float*)d_in[12];
    const float* ff_w2   = (const float*)d_in[13];
    const float* ff_b2   = (const float*)d_in[14];
    const float* fin_w   = (const float*)d_in[15];
    const float* fin_b   = (const float*)d_in[16];
    float* out = (float*)d_out;

    setup_tc_attrs();

    float *p_h,*p_x,*p_qkv,*p_q,*p_k,*p_v,*p_ql,*p_kl,*p_a1,*p_a3,*p_a2;
    float *p_z,*p_z2,*p_p,*p_t,*p_t2,*p_kv,*p_a1z,*p_ao,*p_y,*p_x2,*p_ff;
    cudaGetSymbolAddress((void**)&p_h,  g_h);
    cudaGetSymbolAddress((void**)&p_x,  g_x);
    cudaGetSymbolAddress((void**)&p_qkv,g_qkv);
    cudaGetSymbolAddress((void**)&p_q,  g_q);
    cudaGetSymbolAddress((void**)&p_k,  g_k);
    cudaGetSymbolAddress((void**)&p_v,  g_v);
    cudaGetSymbolAddress((void**)&p_ql, g_ql);
    cudaGetSymbolAddress((void**)&p_kl, g_kl);
    cudaGetSymbolAddress((void**)&p_a1, g_a1);
    cudaGetSymbolAddress((void**)&p_a3, g_a3);
    cudaGetSymbolAddress((void**)&p_a2, g_a2);
    cudaGetSymbolAddress((void**)&p_z,  g_zb);
    cudaGetSymbolAddress((void**)&p_z2, g_zb2);
    cudaGetSymbolAddress((void**)&p_p,  g_pb);
    cudaGetSymbolAddress((void**)&p_t,  g_tb);
    cudaGetSymbolAddress((void**)&p_t2, g_tb2);
    cudaGetSymbolAddress((void**)&p_kv, g_kvb);
    cudaGetSymbolAddress((void**)&p_a1z,g_a1z);
    cudaGetSymbolAddress((void**)&p_ao, g_ao);
    cudaGetSymbolAddress((void**)&p_y,  g_y);
    cudaGetSymbolAddress((void**)&p_x2, g_x2);
    cudaGetSymbolAddress((void**)&p_ff, g_ff);

    const long long MM  = (long long)ML*ML;
    const long long NM  = (long long)NPAD*ML;
    const long long ND  = (long long)NPAD*DHD;
    const long long MD  = (long long)ML*DHD;

    {
        long long tot = (long long)BATCH*LSEQ*DMODEL;
        embed_kernel<<<(unsigned)((tot+255)/256),256>>>(x, enc_emb, pos_emb);
        int tot2 = BATCH*PADL*DMODEL;
        zero_pad_kernel<<<(tot2+255)/256,256>>>();
    }

    for (int lay=0; lay<DEPTH; lay++){
        ln_kernel<<<BATCH*LSEQ,256>>>(p_h, p_x, ln1_s+(long long)lay*DMODEL, ln1_b+(long long)lay*DMODEL, 1);
        // QKV [tensor]
        run_gemm(0,0, BATCH*NPAD, 3*DMODEL, DMODEL,
                 p_x, DMODEL, 0,
                 qkv_w + (long long)lay*DMODEL*3*DMODEL, 3*DMODEL, 0,
                 p_qkv, 3*DMODEL, 0, 1, 1.f, nullptr);
        {
            long long tot = (long long)BH*NPAD*DHD;
            qkv_split_kernel<<<(unsigned)((tot+255)/256),256>>>();
            long long tot2 = (long long)BH*ML*DHD;
            landmark_kernel<<<(unsigned)((tot2+255)/256),256>>>();
        }
        // attn1 = softmax(q @ kl^T)  [tensor TB=1]
        run_gemm(1,0, NPAD, ML, DHD, p_q, DHD, ND, p_kl, DHD, MD, p_a1, ML, NM, BH, 1.f, nullptr);
        softmax_kernel<<<BH*NPAD,128>>>(p_a1, ML);
        // attn2 = softmax(ql @ kl^T)  [tensor TB=1]
        run_gemm(1,0, ML, ML, DHD, p_ql, DHD, MD, p_kl, DHD, MD, p_a2, ML, MM, BH, 1.f, nullptr);
        softmax_kernel<<<BH*ML,128>>>(p_a2, ML);
        // attn3 = softmax(ql @ k^T)  [tensor TB=1]
        run_gemm(1,0, ML, NPAD, DHD, p_ql, DHD, MD, p_k, DHD, ND, p_a3, NPAD, (long long)ML*NPAD, BH, 1.f, nullptr);
        softmax_kernel<<<BH*ML,128>>>(p_a3, NPAD);

        // ---- pinv (tensor, fused aI-X epilogues) ----
        red_init_kernel<<<1,1>>>();
        colsum_kernel<<<(BH*ML+255)/256,256>>>();
        rowsum_kernel<<<(BH*ML+255)/256,256>>>();
        {
            long long tot = (long long)BH*ML*ML;
            unsigned g = (unsigned)((tot+255)/256);
            zinit_kernel<<<g,256>>>();
        }
        float* zc = p_z; float* zn = p_z2;
        for (int it=0; it<6; it++){
            run_gemm(0,6, ML, ML, ML, p_a2, ML, MM, zc, ML, MM, p_p, ML, MM, BH, 7.f, nullptr, p_t);
            run_gemm(0,5, ML, ML, ML, p_p, ML, MM, p_t, ML, MM, p_t2, ML, MM, BH, 15.f, nullptr);
            run_gemm(0,5, ML, ML, ML, p_p, ML, MM, p_t2, ML, MM, p_t, ML, MM, BH, 13.f, nullptr);
            run_gemm(0,0, ML, ML, ML, zc, ML, MM, p_t, ML, MM, zn, ML, MM, BH, 0.25f, nullptr);
            float* tmp = zc; zc = zn; zn = tmp;
        }

        // kv = attn3 @ v  [SIMT N=64]
        run_gemm(0,0, ML, DHD, NPAD, p_a3, NPAD, (long long)ML*NPAD, p_v, DHD, ND, p_kv, DHD, MD, BH, 1.f, nullptr);
        // a1z = attn1 @ Z  [tensor]
        run_gemm(0,0, NPAD, ML, ML, p_a1, ML, NM, zc, ML, MM, p_a1z, ML, NM, BH, 1.f, nullptr);
        // ao = a1z @ kv  [SIMT N=64]
        run_gemm(0,0, NPAD, DHD, ML, p_a1z, ML, NM, p_kv, DHD, MD, p_ao, DHD, ND, BH, 1.f, nullptr);
        {
            long long tot = (long long)BH*NPAD*DHD;
            combine_kernel<<<(unsigned)((tot+255)/256),256>>>(conv_k + (long long)lay*NH*KC);
        }
        // out projection + residual [tensor]
        run_gemm(0,4, BATCH*NPAD, DMODEL, DMODEL,
                 p_y, DMODEL, 0,
                 aout_w + (long long)lay*DMODEL*DMODEL, DMODEL, 0,
                 p_h, DMODEL, 0, 1, 1.f, aout_b + (long long)lay*DMODEL);

        // ---- FFN ----
        ln_kernel<<<BATCH*LSEQ,256>>>(p_h, p_x2, ln2_s+(long long)lay*DMODEL, ln2_b+(long long)lay*DMODEL, 0);
        run_gemm(0,2, BATCH*LSEQ, FFD, DMODEL,
                 p_x2, DMODEL, 0,
                 ff_w1 + (long long)lay*DMODEL*FFD, FFD, 0,
                 p_ff, FFD, 0, 1, 1.f, ff_b1 + (long long)lay*FFD);
        run_gemm(0,3, BATCH*LSEQ, DMODEL, FFD,
                 p_ff, FFD, 0,
                 ff_w2 + (long long)lay*FFD*DMODEL, DMODEL, 0,
                 p_h, DMODEL, 0, 1, 1.f, ff_b2 + (long long)lay*DMODEL);
    }

    final_kernel<<<BATCH,256>>>(fin_w, fin_b, out);
}